// round 1
// baseline (speedup 1.0000x reference)
#include <cuda_runtime.h>
#include <cuda_bf16.h>
#include <math.h>
#include <stdint.h>

// Problem constants
#define BS 512
#define NE 256
#define NQ 64
#define IN_DIM 512
#define EMBED_DIM 512
#define OUT_DIM 512
#define N_HEADS 8
#define HEAD_DIM 64

// Scratch buffers (device globals: allocation-free rule)
__device__ float g_Q[(size_t)BS * NQ * EMBED_DIM];          // 512*64*512   = 64 MB... (fp32)
__device__ float g_KV[(size_t)BS * NE * (2 * EMBED_DIM)];   // 512*256*1024 (K cols [0,512), V cols [512,1024))
__device__ float g_ATTN[(size_t)BS * NQ * EMBED_DIM];

// ---------------------------------------------------------------------------
// Classic SGEMM: C[M,N] = A'[M,K] * B[K,N]   (A' = row-mapped A)
// BM=BN=128, BK=16, 256 threads, 8x8 per thread, 1-deep global prefetch.
// MODE 0: A row m used directly.
// MODE 1: Q gather — logical row m -> physical row (m/64)*256 + (m%64).
// EPI: add bias[n], zero row if post_mask[m] != 0.
// All dims are exact multiples (M%128==0, N%128==0, K%16==0) for this problem.
// ---------------------------------------------------------------------------
template <int MODE, bool EPI>
__global__ void __launch_bounds__(256)
sgemm_kernel(const float* __restrict__ A,
             const float* __restrict__ B,
             float* __restrict__ C,
             int K, int lda, int ldb, int ldc,
             const float* __restrict__ bias,
             const int* __restrict__ post_mask)
{
    __shared__ float As[16][132];   // transposed A tile, padded (2-way max conflict)
    __shared__ float Bs[16][132];

    const int tid = threadIdx.x;
    const int m0 = blockIdx.y << 7;
    const int n0 = blockIdx.x << 7;

    const int arow = tid >> 2;           // 0..63
    const int acol = (tid & 3) << 2;     // 0,4,8,12
    const int brow = tid >> 5;           // 0..7
    const int bcol = (tid & 31) << 2;    // 0..124

    const int tx = tid & 15;
    const int ty = tid >> 4;

    int mA0 = m0 + arow;
    int mA1 = m0 + arow + 64;
    if (MODE == 1) {
        mA0 = ((mA0 >> 6) << 8) | (mA0 & 63);
        mA1 = ((mA1 >> 6) << 8) | (mA1 & 63);
    }
    const float* Ap0 = A + (size_t)mA0 * lda + acol;
    const float* Ap1 = A + (size_t)mA1 * lda + acol;
    const float* Bp0 = B + (size_t)brow * ldb + n0 + bcol;
    const float* Bp1 = B + (size_t)(brow + 8) * ldb + n0 + bcol;

    // prefetch first tile
    float4 a0 = *(const float4*)(Ap0);
    float4 a1 = *(const float4*)(Ap1);
    float4 b0 = *(const float4*)(Bp0);
    float4 b1 = *(const float4*)(Bp1);

    float acc[8][8];
#pragma unroll
    for (int i = 0; i < 8; ++i)
#pragma unroll
        for (int j = 0; j < 8; ++j) acc[i][j] = 0.f;

    for (int k0 = 0;; k0 += 16) {
        // stage regs -> smem
        As[acol + 0][arow] = a0.x;
        As[acol + 1][arow] = a0.y;
        As[acol + 2][arow] = a0.z;
        As[acol + 3][arow] = a0.w;
        As[acol + 0][arow + 64] = a1.x;
        As[acol + 1][arow + 64] = a1.y;
        As[acol + 2][arow + 64] = a1.z;
        As[acol + 3][arow + 64] = a1.w;
        *(float4*)&Bs[brow][bcol] = b0;
        *(float4*)&Bs[brow + 8][bcol] = b1;
        __syncthreads();

        const bool more = (k0 + 16) < K;
        if (more) {
            const int kn = k0 + 16;
            a0 = *(const float4*)(Ap0 + kn);
            a1 = *(const float4*)(Ap1 + kn);
            b0 = *(const float4*)(Bp0 + (size_t)kn * ldb);
            b1 = *(const float4*)(Bp1 + (size_t)kn * ldb);
        }

#pragma unroll
        for (int kk = 0; kk < 16; ++kk) {
            float4 ra0 = *(const float4*)&As[kk][ty << 3];
            float4 ra1 = *(const float4*)&As[kk][(ty << 3) + 4];
            float4 rb0 = *(const float4*)&Bs[kk][tx << 3];
            float4 rb1 = *(const float4*)&Bs[kk][(tx << 3) + 4];
            float ra[8] = {ra0.x, ra0.y, ra0.z, ra0.w, ra1.x, ra1.y, ra1.z, ra1.w};
            float rb[8] = {rb0.x, rb0.y, rb0.z, rb0.w, rb1.x, rb1.y, rb1.z, rb1.w};
#pragma unroll
            for (int i = 0; i < 8; ++i)
#pragma unroll
                for (int j = 0; j < 8; ++j)
                    acc[i][j] = fmaf(ra[i], rb[j], acc[i][j]);
        }
        if (!more) break;
        __syncthreads();
    }

    // epilogue
#pragma unroll
    for (int i = 0; i < 8; ++i) {
        const int m = m0 + (ty << 3) + i;
        bool zero = false;
        if (EPI) zero = (post_mask[m] != 0);
        float* cp = C + (size_t)m * ldc + n0 + (tx << 3);
#pragma unroll
        for (int j = 0; j < 8; j += 4) {
            float4 v;
            v.x = acc[i][j + 0];
            v.y = acc[i][j + 1];
            v.z = acc[i][j + 2];
            v.w = acc[i][j + 3];
            if (EPI) {
                const int n = n0 + (tx << 3) + j;
                v.x += bias[n + 0];
                v.y += bias[n + 1];
                v.z += bias[n + 2];
                v.w += bias[n + 3];
                if (zero) { v.x = 0.f; v.y = 0.f; v.z = 0.f; v.w = 0.f; }
            }
            *(float4*)(cp + j) = v;
        }
    }
}

// ---------------------------------------------------------------------------
// Attention kernel: one block per (head, batch). 256 threads.
// S = (Q/8) @ K^T with pre_mask -> -inf; softmax over 256 keys (all-masked
// row -> zero weights); A = P @ V. Q/K/V chunks staged in smem.
// Dynamic smem: sQ 64x68 | sKV 64x68 | sS 64x257 | sRed 256 | sInv 64
// ---------------------------------------------------------------------------
#define SQ_STRIDE 68
#define SS_STRIDE 257
#define SM_SQ 0
#define SM_SKV (64 * SQ_STRIDE)
#define SM_SS (2 * 64 * SQ_STRIDE)
#define SM_SRED (SM_SS + 64 * SS_STRIDE)
#define SM_SINV (SM_SRED + 256)
#define ATTN_SMEM_FLOATS (SM_SINV + 64)
#define ATTN_SMEM_BYTES (ATTN_SMEM_FLOATS * 4)

__global__ void __launch_bounds__(256)
attn_kernel(const float* __restrict__ Q,
            const float* __restrict__ KV,
            const int* __restrict__ pre_mask,
            float* __restrict__ ATTN)
{
    extern __shared__ float sm[];
    float* sQ = sm + SM_SQ;
    float* sKV = sm + SM_SKV;
    float* sS = sm + SM_SS;
    float* sRed = sm + SM_SRED;
    float* sInv = sm + SM_SINV;

    const int tid = threadIdx.x;
    const int h = blockIdx.x;
    const int bs = blockIdx.y;

    const int lq = tid >> 4;            // 0..15 (row for cooperative loads)
    const int ld4 = (tid & 15) << 2;    // 0..60 step 4

    const float NEG_INF = -INFINITY;

    // ---- load Q tile, folding 1/sqrt(HEAD_DIM) = 1/8 ----
#pragma unroll
    for (int it = 0; it < 4; ++it) {
        const int qi = lq + (it << 4);
        float4 v = *(const float4*)(Q + ((size_t)bs * NQ + qi) * EMBED_DIM + h * HEAD_DIM + ld4);
        float* dst = &sQ[qi * SQ_STRIDE + ld4];
        dst[0] = v.x * 0.125f;
        dst[1] = v.y * 0.125f;
        dst[2] = v.z * 0.125f;
        dst[3] = v.w * 0.125f;
    }

    const int qi = tid >> 2;    // 0..63
    const int kg = tid & 3;     // 0..3

    // ---- S = scaled Q @ K^T, masked, in 4 chunks of 64 keys ----
    for (int c = 0; c < 4; ++c) {
        __syncthreads();   // prev chunk consumers done (and Q stores visible before 1st compute)
#pragma unroll
        for (int it = 0; it < 4; ++it) {
            const int e = lq + (it << 4);
            float4 v = *(const float4*)(KV + ((size_t)bs * NE + (c << 6) + e) * (2 * EMBED_DIM)
                                        + h * HEAD_DIM + ld4);
            float* dst = &sKV[e * SQ_STRIDE + ld4];
            dst[0] = v.x; dst[1] = v.y; dst[2] = v.z; dst[3] = v.w;
        }
        __syncthreads();

#pragma unroll 4
        for (int j = 0; j < 16; ++j) {
            const int k = kg + (j << 2);
            float s = 0.f;
#pragma unroll
            for (int d = 0; d < 64; d += 4) {
                float4 a = *(const float4*)&sQ[qi * SQ_STRIDE + d];
                float4 b = *(const float4*)&sKV[k * SQ_STRIDE + d];
                s = fmaf(a.x, b.x, s);
                s = fmaf(a.y, b.y, s);
                s = fmaf(a.z, b.z, s);
                s = fmaf(a.w, b.w, s);
            }
            const int kglob = (c << 6) + k;
            const int msk = pre_mask[((size_t)bs * NQ + qi) * NE + kglob];
            sS[qi * SS_STRIDE + kglob] = msk ? NEG_INF : s;
        }
    }
    __syncthreads();

    // ---- softmax over 256 keys per row (4 threads/row) ----
    const int row = tid >> 2;
    const int part = tid & 3;
    const int kbeg = part << 6;

    float mx = NEG_INF;
    for (int k = 0; k < 64; ++k)
        mx = fmaxf(mx, sS[row * SS_STRIDE + kbeg + k]);
    sRed[(row << 2) + part] = mx;
    __syncthreads();
    const float rm = fmaxf(fmaxf(sRed[row << 2], sRed[(row << 2) + 1]),
                           fmaxf(sRed[(row << 2) + 2], sRed[(row << 2) + 3]));
    __syncthreads();   // before sRed reuse

    const bool live = (rm != NEG_INF);
    float ssum = 0.f;
    for (int k = 0; k < 64; ++k) {
        const float v = sS[row * SS_STRIDE + kbeg + k];
        float e = 0.f;
        if (live && v != NEG_INF) e = __expf(v - rm);
        sS[row * SS_STRIDE + kbeg + k] = e;   // unnormalized weights
        ssum += e;
    }
    sRed[(row << 2) + part] = ssum;
    __syncthreads();
    if (tid < 64) {
        const float t = sRed[tid << 2] + sRed[(tid << 2) + 1] +
                        sRed[(tid << 2) + 2] + sRed[(tid << 2) + 3];
        sInv[tid] = (t > 0.f) ? (1.f / t) : 0.f;
    }

    // ---- A = P @ V (per-thread: one q-row, 16 of 64 dims) ----
    const int dg = tid & 3;            // dim group (16 dims each)
    float acc[16];
#pragma unroll
    for (int j = 0; j < 16; ++j) acc[j] = 0.f;

    for (int c = 0; c < 4; ++c) {
        __syncthreads();   // sKV free; first iter also orders sInv/sS writes
#pragma unroll
        for (int it = 0; it < 4; ++it) {
            const int e = lq + (it << 4);
            float4 v = *(const float4*)(KV + ((size_t)bs * NE + (c << 6) + e) * (2 * EMBED_DIM)
                                        + EMBED_DIM + h * HEAD_DIM + ld4);
            float* dst = &sKV[e * SQ_STRIDE + ld4];
            dst[0] = v.x; dst[1] = v.y; dst[2] = v.z; dst[3] = v.w;
        }
        __syncthreads();

        for (int k = 0; k < 64; ++k) {
            const float w = sS[qi * SS_STRIDE + (c << 6) + k];
            const float* vp = &sKV[k * SQ_STRIDE + (dg << 4)];
            float4 v0 = *(const float4*)(vp);
            float4 v1 = *(const float4*)(vp + 4);
            float4 v2 = *(const float4*)(vp + 8);
            float4 v3 = *(const float4*)(vp + 12);
            acc[0]  = fmaf(w, v0.x, acc[0]);
            acc[1]  = fmaf(w, v0.y, acc[1]);
            acc[2]  = fmaf(w, v0.z, acc[2]);
            acc[3]  = fmaf(w, v0.w, acc[3]);
            acc[4]  = fmaf(w, v1.x, acc[4]);
            acc[5]  = fmaf(w, v1.y, acc[5]);
            acc[6]  = fmaf(w, v1.z, acc[6]);
            acc[7]  = fmaf(w, v1.w, acc[7]);
            acc[8]  = fmaf(w, v2.x, acc[8]);
            acc[9]  = fmaf(w, v2.y, acc[9]);
            acc[10] = fmaf(w, v2.z, acc[10]);
            acc[11] = fmaf(w, v2.w, acc[11]);
            acc[12] = fmaf(w, v3.x, acc[12]);
            acc[13] = fmaf(w, v3.y, acc[13]);
            acc[14] = fmaf(w, v3.z, acc[14]);
            acc[15] = fmaf(w, v3.w, acc[15]);
        }
    }

    const float inv = sInv[qi];
    float* op = ATTN + ((size_t)bs * NQ + qi) * EMBED_DIM + h * HEAD_DIM + (dg << 4);
#pragma unroll
    for (int j = 0; j < 16; j += 4) {
        float4 v;
        v.x = acc[j + 0] * inv;
        v.y = acc[j + 1] * inv;
        v.z = acc[j + 2] * inv;
        v.w = acc[j + 3] * inv;
        *(float4*)(op + j) = v;
    }
}

// ---------------------------------------------------------------------------
// kernel_launch
// ---------------------------------------------------------------------------
extern "C" void kernel_launch(void* const* d_in, const int* in_sizes, int n_in,
                              void* d_out, int out_size)
{
    const float* entities  = (const float*)d_in[0];   // [512,256,512]
    const int*   pre_mask  = (const int*)d_in[1];     // [512,64,256]
    const int*   post_mask = (const int*)d_in[2];     // [512,64]
    const float* W_in      = (const float*)d_in[3];   // [512,1536]
    const float* W_out     = (const float*)d_in[4];   // [512,512]
    const float* b_out     = (const float*)d_in[5];   // [512]
    float* out = (float*)d_out;                       // [512,64,512]

    float* Qs;   cudaGetSymbolAddress((void**)&Qs, g_Q);
    float* KVs;  cudaGetSymbolAddress((void**)&KVs, g_KV);
    float* ATs;  cudaGetSymbolAddress((void**)&ATs, g_ATTN);

    cudaFuncSetAttribute(attn_kernel,
                         cudaFuncAttributeMaxDynamicSharedMemorySize,
                         ATTN_SMEM_BYTES);

    // 1) Q = entities[:, :64, :] @ W_in[:, 0:512]      M=32768, N=512, K=512
    sgemm_kernel<1, false><<<dim3(512 / 128, 32768 / 128), 256>>>(
        entities, W_in, Qs, IN_DIM, IN_DIM, 3 * EMBED_DIM, EMBED_DIM,
        nullptr, nullptr);

    // 2) KV = entities @ W_in[:, 512:1536]             M=131072, N=1024, K=512
    sgemm_kernel<0, false><<<dim3(1024 / 128, 131072 / 128), 256>>>(
        entities, W_in + EMBED_DIM, KVs, IN_DIM, IN_DIM, 3 * EMBED_DIM,
        2 * EMBED_DIM, nullptr, nullptr);

    // 3) attention: grid = (heads, batch)
    attn_kernel<<<dim3(N_HEADS, BS), 256, ATTN_SMEM_BYTES>>>(
        Qs, KVs, pre_mask, ATs);

    // 4) out = ATTN @ W_out + b_out, post-masked       M=32768, N=512, K=512
    sgemm_kernel<0, true><<<dim3(512 / 128, 32768 / 128), 256>>>(
        ATs, W_out, out, EMBED_DIM, EMBED_DIM, OUT_DIM, OUT_DIM,
        b_out, post_mask);
}

// round 3
// speedup vs baseline: 1.8717x; 1.8717x over previous
#include <cuda_runtime.h>
#include <cuda_bf16.h>
#include <math.h>
#include <stdint.h>

// Problem constants
#define BS 512
#define NE 256
#define NQ 64
#define IN_DIM 512
#define EMBED_DIM 512
#define OUT_DIM 512
#define N_HEADS 8
#define HEAD_DIM 64
#define QKV_DIM (3 * EMBED_DIM)

// Arch-feature gate: tcgen05 only exists in arch-specific (sm_103a/sm_100a) passes.
#if defined(__CUDA_ARCH__) && (defined(__CUDA_ARCH_FEAT_SM103_ALL) || defined(__CUDA_ARCH_FEAT_SM100_ALL) || defined(__CUDA_ARCH_FEAT_SM101_ALL))
#define HAS_TCGEN05 1
#else
#define HAS_TCGEN05 0
#endif

// ---------------------------------------------------------------------------
// Scratch (device globals: allocation-free rule)
// ---------------------------------------------------------------------------
__device__ float g_Q[(size_t)BS * NQ * EMBED_DIM];
__device__ float g_KV[(size_t)BS * NE * (2 * EMBED_DIM)];
__device__ float g_ATTN[(size_t)BS * NQ * EMBED_DIM];
__device__ __nv_bfloat16 g_ent_hi[(size_t)BS * NE * IN_DIM];
__device__ __nv_bfloat16 g_ent_lo[(size_t)BS * NE * IN_DIM];
__device__ __nv_bfloat16 g_attn_hi[(size_t)BS * NQ * EMBED_DIM];
__device__ __nv_bfloat16 g_attn_lo[(size_t)BS * NQ * EMBED_DIM];
__device__ __nv_bfloat16 g_WinT_hi[(size_t)QKV_DIM * IN_DIM];
__device__ __nv_bfloat16 g_WinT_lo[(size_t)QKV_DIM * IN_DIM];
__device__ __nv_bfloat16 g_WoutT_hi[(size_t)OUT_DIM * EMBED_DIM];
__device__ __nv_bfloat16 g_WoutT_lo[(size_t)OUT_DIM * EMBED_DIM];

// ---------------------------------------------------------------------------
// Common helpers (arch-neutral)
// ---------------------------------------------------------------------------
__device__ __forceinline__ uint32_t smem_u32(const void* p) {
    uint32_t a;
    asm("{ .reg .u64 t; cvta.to.shared.u64 t, %1; cvt.u32.u64 %0, t; }" : "=r"(a) : "l"(p));
    return a;
}
__device__ __forceinline__ void cp16(uint32_t s, const void* g) {
    asm volatile("cp.async.cg.shared.global [%0], [%1], 16;" :: "r"(s), "l"(g) : "memory");
}
__device__ __forceinline__ void ldsm4(uint32_t* r, uint32_t addr) {
    asm volatile("ldmatrix.sync.aligned.m8n8.x4.shared.b16 {%0,%1,%2,%3}, [%4];"
                 : "=r"(r[0]), "=r"(r[1]), "=r"(r[2]), "=r"(r[3]) : "r"(addr));
}
__device__ __forceinline__ void mma_bf16(float* d, const uint32_t* a, const uint32_t* b) {
    asm volatile("mma.sync.aligned.m16n8k16.row.col.f32.bf16.bf16.f32 "
                 "{%0,%1,%2,%3}, {%4,%5,%6,%7}, {%8,%9}, {%0,%1,%2,%3};"
                 : "+f"(d[0]), "+f"(d[1]), "+f"(d[2]), "+f"(d[3])
                 : "r"(a[0]), "r"(a[1]), "r"(a[2]), "r"(a[3]), "r"(b[0]), "r"(b[1]));
}

#if HAS_TCGEN05
// ---------------------------------------------------------------------------
// tcgen05 helpers (arch-specific pass only)
// ---------------------------------------------------------------------------
__device__ __forceinline__ uint32_t elect_one_pred() {
    uint32_t p;
    asm volatile("{\n\t.reg .pred p;\n\telect.sync _|p, 0xFFFFFFFF;\n\tselp.b32 %0, 1, 0, p;\n\t}" : "=r"(p));
    return p;
}
#define TCGEN05_ALLOC(sa, n) \
    asm volatile("tcgen05.alloc.cta_group::1.sync.aligned.shared::cta.b32 [%0], %1;" :: "r"((uint32_t)(sa)), "r"((uint32_t)(n)) : "memory")
#define TCGEN05_DEALLOC(t, n) \
    asm volatile("tcgen05.dealloc.cta_group::1.sync.aligned.b32 %0, %1;" :: "r"(t), "r"((uint32_t)(n)))
#define TCGEN05_RELINQ() \
    asm volatile("tcgen05.relinquish_alloc_permit.cta_group::1.sync.aligned;")
#define TCGEN05_COMMIT(mb) \
    asm volatile("tcgen05.commit.cta_group::1.mbarrier::arrive::one.shared::cluster.b64 [%0];" :: "r"((uint32_t)(mb)) : "memory")
#define TCGEN05_FENCE_AFTER() asm volatile("tcgen05.fence::after_thread_sync;" ::: "memory")
#define TCGEN05_FENCE_BEFORE() asm volatile("tcgen05.fence::before_thread_sync;" ::: "memory")
#define TCGEN05_WAIT_LD() asm volatile("tcgen05.wait::ld.sync.aligned;" ::: "memory")
#define FENCE_PROXY_ASYNC() asm volatile("fence.proxy.async;" ::: "memory")
#define MBARRIER_INIT(mb, cnt) \
    asm volatile("mbarrier.init.shared.b64 [%0], %1;" :: "r"((uint32_t)(mb)), "r"((uint32_t)(cnt)) : "memory")
#define MBARRIER_INVAL(mb) \
    asm volatile("mbarrier.inval.shared.b64 [%0];" :: "r"((uint32_t)(mb)) : "memory")
#define MBARRIER_WAIT_PARITY(mb, par) do {                                           \
    uint32_t _mb = (uint32_t)(mb); uint32_t _p = (uint32_t)(par); uint32_t _d;       \
    asm volatile("{\n\t.reg .pred p;\n\t"                                            \
        "mbarrier.try_wait.parity.acquire.cta.shared::cta.b64 p, [%1], %2;\n\t"      \
        "selp.b32 %0, 1, 0, p;\n\t}" : "=r"(_d) : "r"(_mb), "r"(_p) : "memory");     \
    if (!_d) {                                                                       \
        asm volatile("{\n\t.reg .pred P1;\n\t"                                       \
            "WL_%=:\n\t"                                                             \
            "mbarrier.try_wait.parity.acquire.cta.shared::cta.b64 P1, [%0], %1, 0x989680;\n\t" \
            "@P1 bra.uni WD_%=;\n\t"                                                 \
            "bra.uni WL_%=;\n\t"                                                     \
            "WD_%=:\n\t}" :: "r"(_mb), "r"(_p) : "memory");                          \
    }                                                                                \
} while (0)

#define TCGEN05_LD_32X32B_X32(r, ta) \
    asm volatile( \
        "tcgen05.ld.sync.aligned.32x32b.x32.b32 " \
        "{%0, %1, %2, %3, %4, %5, %6, %7, " \
        " %8, %9, %10, %11, %12, %13, %14, %15, " \
        " %16, %17, %18, %19, %20, %21, %22, %23, " \
        " %24, %25, %26, %27, %28, %29, %30, %31}, [%32];" \
        : "=r"((r)[0]),  "=r"((r)[1]),  "=r"((r)[2]),  "=r"((r)[3]), \
          "=r"((r)[4]),  "=r"((r)[5]),  "=r"((r)[6]),  "=r"((r)[7]), \
          "=r"((r)[8]),  "=r"((r)[9]),  "=r"((r)[10]), "=r"((r)[11]), \
          "=r"((r)[12]), "=r"((r)[13]), "=r"((r)[14]), "=r"((r)[15]), \
          "=r"((r)[16]), "=r"((r)[17]), "=r"((r)[18]), "=r"((r)[19]), \
          "=r"((r)[20]), "=r"((r)[21]), "=r"((r)[22]), "=r"((r)[23]), \
          "=r"((r)[24]), "=r"((r)[25]), "=r"((r)[26]), "=r"((r)[27]), \
          "=r"((r)[28]), "=r"((r)[29]), "=r"((r)[30]), "=r"((r)[31]) \
        : "r"(ta))

static constexpr uint64_t SMEM_DESC_BASE_SW128 =
    (uint64_t(2) << 61) | (uint64_t(1) << 46) | (uint64_t(64) << 32) | (uint64_t(1) << 16);
#define MAKE_SMEM_DESC(ba) (SMEM_DESC_BASE_SW128 | ((uint64_t)((ba) >> 4) & 0x3FFF))

__device__ __forceinline__ void mma_bf16_ss(uint32_t d, uint64_t da, uint64_t db,
                                            uint32_t idesc, bool en) {
    uint32_t e = en ? 1u : 0u;
    asm volatile(
        "{\n\t.reg .pred p;\n\t"
        "setp.ne.u32 p, %4, 0;\n\t"
        "tcgen05.mma.cta_group::1.kind::f16 [%0], %1, %2, %3, {%5, %5, %5, %5}, p;\n\t"
        "}"
        :: "r"(d), "l"(da), "l"(db), "r"(idesc), "r"(e), "r"(0u)
        : "memory");
}
// idesc: f32 accum, bf16 a, bf16 b, N=128, M=128
static constexpr uint32_t MMA_IDESC =
    (1u << 4) | (1u << 7) | (1u << 10) | ((128u / 8) << 17) | ((128u / 16) << 24);
#endif // HAS_TCGEN05

// ---------------------------------------------------------------------------
// bf16x3 GEMM: C[M,N] = A[M,512] @ Bt[N,512]^T  (K-major, K=512)
// CTA tile 128x128. Two implementations under one entry:
//   tcgen05 SS-mode MMA path (arch-specific pass), mma.sync HMMA fallback.
// MODE 1: A row gather (Q): logical m -> (m/64)*256 + (m%64).
// EPI: +bias[n], zero row if post_mask[m].
// ---------------------------------------------------------------------------
#define GK 512
#define GKCHUNK 64
#define NCHUNKS 8
#define TILE_BYTES 16384
#define STAGE_BYTES (4 * TILE_BYTES)   // Ahi | Alo | Bhi | Blo
#define NSTAGES 3
#define GEMM_DYN_SMEM (NSTAGES * STAGE_BYTES + 1024)

template <int MODE, bool EPI>
__global__ void __launch_bounds__(256, 1)
gemm_bf16x3(const __nv_bfloat16* __restrict__ Ahi, const __nv_bfloat16* __restrict__ Alo,
            const __nv_bfloat16* __restrict__ Bhi, const __nv_bfloat16* __restrict__ Blo,
            float* __restrict__ C, int ldc,
            const float* __restrict__ bias, const int* __restrict__ post_mask)
{
    extern __shared__ char dyn_smem[];
    const int tid = threadIdx.x;
    const int wid = tid >> 5;
    const int lane = tid & 31;
    const int m0 = blockIdx.y << 7;
    const int n0 = blockIdx.x << 7;

    const uint32_t sbase = (smem_u32(dyn_smem) + 1023u) & ~1023u;

    // cooperative cp.async of one K-chunk (64 cols bf16 = 128B/row) into stage st
    auto issue_loads = [&](int ch, int st) {
        const uint32_t sb = sbase + st * STAGE_BYTES;
        const int koff = ch * GKCHUNK;
#pragma unroll
        for (int i = 0; i < 4; ++i) {
            const int idx = tid + (i << 8);
            const int row = idx >> 3;
            const int piece = idx & 7;
            const uint32_t off = (row << 7) + (piece << 4);
            const uint32_t sw = off ^ ((off >> 3) & 0x70);
            int grow = m0 + row;
            if (MODE == 1) grow = ((grow >> 6) << 8) | (grow & 63);
            const size_t gA = (size_t)grow * GK + koff + piece * 8;
            const size_t gB = (size_t)(n0 + row) * GK + koff + piece * 8;
            cp16(sb + sw, Ahi + gA);
            cp16(sb + TILE_BYTES + sw, Alo + gA);
            cp16(sb + 2 * TILE_BYTES + sw, Bhi + gB);
            cp16(sb + 3 * TILE_BYTES + sw, Blo + gB);
        }
        asm volatile("cp.async.commit_group;" ::: "memory");
    };

#if HAS_TCGEN05
    // =============================== tcgen05 path ===========================
    __shared__ uint32_t s_tmem_ptr[2];
    __shared__ __align__(8) uint64_t s_mbar[NSTAGES];

    if (wid == 0) {
        TCGEN05_ALLOC(smem_u32(s_tmem_ptr), 128);
        TCGEN05_RELINQ();
    }
    if (tid == 0) {
#pragma unroll
        for (int j = 0; j < NSTAGES; ++j) MBARRIER_INIT(smem_u32(&s_mbar[j]), 1);
    }
    __syncthreads();

    uint32_t tmem_base;
    asm volatile("ld.shared.b32 %0, [%1];" : "=r"(tmem_base) : "r"(smem_u32(s_tmem_ptr)));

    uint32_t mb_addr[NSTAGES];
#pragma unroll
    for (int j = 0; j < NSTAGES; ++j) mb_addr[j] = smem_u32(&s_mbar[j]);

    issue_loads(0, 0);
    issue_loads(1, 1);

    int ph[NSTAGES] = {0, 0, 0};

    for (int c = 0; c < NCHUNKS; ++c) {
        const int st = c % NSTAGES;
        if (c < NCHUNKS - 1) asm volatile("cp.async.wait_group 1;" ::: "memory");
        else                 asm volatile("cp.async.wait_group 0;" ::: "memory");
        __syncthreads();

        if (wid == 0) {
            if (elect_one_pred()) {
                FENCE_PROXY_ASYNC();
                const uint32_t sb = sbase + st * STAGE_BYTES;
                const uint64_t dAhi = MAKE_SMEM_DESC(sb);
                const uint64_t dAlo = MAKE_SMEM_DESC(sb + TILE_BYTES);
                const uint64_t dBhi = MAKE_SMEM_DESC(sb + 2 * TILE_BYTES);
                const uint64_t dBlo = MAKE_SMEM_DESC(sb + 3 * TILE_BYTES);
#pragma unroll
                for (int s = 0; s < 4; ++s) {
                    const bool first = (c == 0) && (s == 0);
                    mma_bf16_ss(tmem_base, dAhi + 2 * s, dBhi + 2 * s, MMA_IDESC, !first);
                    mma_bf16_ss(tmem_base, dAhi + 2 * s, dBlo + 2 * s, MMA_IDESC, true);
                    mma_bf16_ss(tmem_base, dAlo + 2 * s, dBhi + 2 * s, MMA_IDESC, true);
                }
                TCGEN05_COMMIT(mb_addr[st]);
            }
        }

        // wait for chunk c-1's MMAs: frees stage (c-1)%3 == (c+2)%3 for next loads
        if (c >= 1) {
            const int w = (c - 1) % NSTAGES;
            MBARRIER_WAIT_PARITY(mb_addr[w], ph[w]);
            ph[w] ^= 1;
        }
        if (c + 2 < NCHUNKS) issue_loads(c + 2, (c + 2) % NSTAGES);
    }
    // drain: only chunk NCHUNKS-1 remains unwaited
    {
        const int w = (NCHUNKS - 1) % NSTAGES;
        MBARRIER_WAIT_PARITY(mb_addr[w], ph[w]);
        ph[w] ^= 1;
    }
    TCGEN05_FENCE_AFTER();

    // epilogue: warp (wid&3) -> 32-row subpartition, (wid>>2) -> column half
    {
        const int rsub = (wid & 3) << 5;
        const int colh = (wid >> 2) << 6;
        const int m = m0 + rsub + lane;
        bool zero = false;
        if (EPI) zero = (post_mask[m] != 0);
        float* crow = C + (size_t)m * ldc + n0;

#pragma unroll
        for (int half = 0; half < 2; ++half) {
            const int cbase = colh + half * 32;
            uint32_t r[32];
            TCGEN05_LD_32X32B_X32(r, tmem_base + cbase);
            TCGEN05_WAIT_LD();
#pragma unroll
            for (int j = 0; j < 32; j += 4) {
                float4 v;
                v.x = __uint_as_float(r[j + 0]);
                v.y = __uint_as_float(r[j + 1]);
                v.z = __uint_as_float(r[j + 2]);
                v.w = __uint_as_float(r[j + 3]);
                if (EPI) {
                    const int n = n0 + cbase + j;
                    v.x += bias[n + 0];
                    v.y += bias[n + 1];
                    v.z += bias[n + 2];
                    v.w += bias[n + 3];
                    if (zero) { v.x = 0.f; v.y = 0.f; v.z = 0.f; v.w = 0.f; }
                }
                *(float4*)(crow + cbase + j) = v;
            }
        }
        TCGEN05_FENCE_BEFORE();
    }

    __syncthreads();
    if (tid == 0) {
#pragma unroll
        for (int j = 0; j < NSTAGES; ++j) MBARRIER_INVAL(mb_addr[j]);
    }
    __syncthreads();
    if (wid == 0) TCGEN05_DEALLOC(tmem_base, 128);

#else
    // =========================== mma.sync fallback ==========================
    // 8 warps as 2(m) x 4(n): warp tile 64x32. m16n8k16 HMMA, 3-product split.
    const int wm = (wid & 1) << 6;
    const int wn = (wid >> 1) << 5;

    float acc[4][4][4];
#pragma unroll
    for (int a = 0; a < 4; ++a)
#pragma unroll
        for (int b = 0; b < 4; ++b)
#pragma unroll
            for (int d = 0; d < 4; ++d) acc[a][b][d] = 0.f;

    issue_loads(0, 0);
    issue_loads(1, 1);

    for (int c = 0; c < NCHUNKS; ++c) {
        if (c < NCHUNKS - 1) asm volatile("cp.async.wait_group 1;" ::: "memory");
        else                 asm volatile("cp.async.wait_group 0;" ::: "memory");
        __syncthreads();
        const uint32_t sb = sbase + (c & 1) * STAGE_BYTES;

#pragma unroll
        for (int ks = 0; ks < 4; ++ks) {
            uint32_t ahi[4][4], alo[4][4];
#pragma unroll
            for (int mf = 0; mf < 4; ++mf) {
                const uint32_t row = wm + (mf << 4) + (lane & 15);
                const uint32_t kp = (ks << 1) + (lane >> 4);
                const uint32_t off = (row << 7) + (kp << 4);
                const uint32_t sw = off ^ ((off >> 3) & 0x70);
                ldsm4(ahi[mf], sb + sw);
                ldsm4(alo[mf], sb + TILE_BYTES + sw);
            }
            uint32_t bhi[4][2], blo[4][2];
#pragma unroll
            for (int nb = 0; nb < 2; ++nb) {
                const uint32_t row = wn + (nb << 4) + ((lane >> 4) << 3) + (lane & 7);
                const uint32_t kp = (ks << 1) + ((lane >> 3) & 1);
                const uint32_t off = (row << 7) + (kp << 4);
                const uint32_t sw = off ^ ((off >> 3) & 0x70);
                uint32_t t[4];
                ldsm4(t, sb + 2 * TILE_BYTES + sw);
                bhi[2 * nb][0] = t[0]; bhi[2 * nb][1] = t[1];
                bhi[2 * nb + 1][0] = t[2]; bhi[2 * nb + 1][1] = t[3];
                ldsm4(t, sb + 3 * TILE_BYTES + sw);
                blo[2 * nb][0] = t[0]; blo[2 * nb][1] = t[1];
                blo[2 * nb + 1][0] = t[2]; blo[2 * nb + 1][1] = t[3];
            }
#pragma unroll
            for (int mf = 0; mf < 4; ++mf)
#pragma unroll
                for (int nf = 0; nf < 4; ++nf) {
                    mma_bf16(acc[mf][nf], ahi[mf], bhi[nf]);
                    mma_bf16(acc[mf][nf], ahi[mf], blo[nf]);
                    mma_bf16(acc[mf][nf], alo[mf], bhi[nf]);
                }
        }
        __syncthreads();
        if (c + 2 < NCHUNKS) issue_loads(c + 2, (c + 2) & 1);
    }

    // epilogue: d0,d1 -> row lane/4, cols c,c+1; d2,d3 -> row+8
#pragma unroll
    for (int mf = 0; mf < 4; ++mf) {
#pragma unroll
        for (int half = 0; half < 2; ++half) {
            const int m = m0 + wm + (mf << 4) + (half << 3) + (lane >> 2);
            bool zero = false;
            if (EPI) zero = (post_mask[m] != 0);
            float* crow = C + (size_t)m * ldc;
#pragma unroll
            for (int nf = 0; nf < 4; ++nf) {
                const int col = n0 + wn + (nf << 3) + ((lane & 3) << 1);
                float v0 = acc[mf][nf][half * 2 + 0];
                float v1 = acc[mf][nf][half * 2 + 1];
                if (EPI) {
                    v0 += bias[col];
                    v1 += bias[col + 1];
                    if (zero) { v0 = 0.f; v1 = 0.f; }
                }
                crow[col] = v0;
                crow[col + 1] = v1;
            }
        }
    }
#endif
}

// ---------------------------------------------------------------------------
// fp32 -> bf16 hi/lo split (vectorized)
// ---------------------------------------------------------------------------
__global__ void __launch_bounds__(256)
split_kernel(const float* __restrict__ in, __nv_bfloat16* __restrict__ hi,
             __nv_bfloat16* __restrict__ lo, int n4)
{
    int i = blockIdx.x * blockDim.x + threadIdx.x;
    if (i >= n4) return;
    float4 v = ((const float4*)in)[i];
    __nv_bfloat16 h0 = __float2bfloat16(v.x);
    __nv_bfloat16 h1 = __float2bfloat16(v.y);
    __nv_bfloat16 h2 = __float2bfloat16(v.z);
    __nv_bfloat16 h3 = __float2bfloat16(v.w);
    __nv_bfloat16 l0 = __float2bfloat16(v.x - __bfloat162float(h0));
    __nv_bfloat16 l1 = __float2bfloat16(v.y - __bfloat162float(h1));
    __nv_bfloat16 l2 = __float2bfloat16(v.z - __bfloat162float(h2));
    __nv_bfloat16 l3 = __float2bfloat16(v.w - __bfloat162float(h3));
    __nv_bfloat162 ph0; ph0.x = h0; ph0.y = h1;
    __nv_bfloat162 ph1; ph1.x = h2; ph1.y = h3;
    __nv_bfloat162 pl0; pl0.x = l0; pl0.y = l1;
    __nv_bfloat162 pl1; pl1.x = l2; pl1.y = l3;
    ((__nv_bfloat162*)hi)[2 * i + 0] = ph0;
    ((__nv_bfloat162*)hi)[2 * i + 1] = ph1;
    ((__nv_bfloat162*)lo)[2 * i + 0] = pl0;
    ((__nv_bfloat162*)lo)[2 * i + 1] = pl1;
}

// fp32 [K,N] -> bf16 hi/lo transposed [N,K]
__global__ void __launch_bounds__(256)
splitT_kernel(const float* __restrict__ in, __nv_bfloat16* __restrict__ hiT,
              __nv_bfloat16* __restrict__ loT, int Kd, int Nd)
{
    int i = blockIdx.x * blockDim.x + threadIdx.x;
    if (i >= Kd * Nd) return;
    int k = i / Nd, n = i % Nd;
    float x = in[i];
    __nv_bfloat16 h = __float2bfloat16(x);
    __nv_bfloat16 l = __float2bfloat16(x - __bfloat162float(h));
    hiT[(size_t)n * Kd + k] = h;
    loT[(size_t)n * Kd + k] = l;
}

// ---------------------------------------------------------------------------
// Attention kernel (Round-1 proven version; Q ld=512, KV ld=1024)
// ---------------------------------------------------------------------------
#define SQ_STRIDE 68
#define SS_STRIDE 257
#define SM_SQ 0
#define SM_SKV (64 * SQ_STRIDE)
#define SM_SS (2 * 64 * SQ_STRIDE)
#define SM_SRED (SM_SS + 64 * SS_STRIDE)
#define SM_SINV (SM_SRED + 256)
#define ATTN_SMEM_FLOATS (SM_SINV + 64)
#define ATTN_SMEM_BYTES (ATTN_SMEM_FLOATS * 4)

__global__ void __launch_bounds__(256)
attn_kernel(const float* __restrict__ Q,
            const float* __restrict__ KV,
            const int* __restrict__ pre_mask,
            float* __restrict__ ATTN)
{
    extern __shared__ float sm[];
    float* sQ = sm + SM_SQ;
    float* sKV = sm + SM_SKV;
    float* sS = sm + SM_SS;
    float* sRed = sm + SM_SRED;
    float* sInv = sm + SM_SINV;

    const int tid = threadIdx.x;
    const int h = blockIdx.x;
    const int bs = blockIdx.y;

    const int lq = tid >> 4;
    const int ld4 = (tid & 15) << 2;

    const float NEG_INF = -INFINITY;

#pragma unroll
    for (int it = 0; it < 4; ++it) {
        const int qi = lq + (it << 4);
        float4 v = *(const float4*)(Q + ((size_t)bs * NQ + qi) * EMBED_DIM + h * HEAD_DIM + ld4);
        float* dst = &sQ[qi * SQ_STRIDE + ld4];
        dst[0] = v.x * 0.125f;
        dst[1] = v.y * 0.125f;
        dst[2] = v.z * 0.125f;
        dst[3] = v.w * 0.125f;
    }

    const int qi = tid >> 2;
    const int kg = tid & 3;

    for (int c = 0; c < 4; ++c) {
        __syncthreads();
#pragma unroll
        for (int it = 0; it < 4; ++it) {
            const int e = lq + (it << 4);
            float4 v = *(const float4*)(KV + ((size_t)bs * NE + (c << 6) + e) * (2 * EMBED_DIM)
                                        + h * HEAD_DIM + ld4);
            float* dst = &sKV[e * SQ_STRIDE + ld4];
            dst[0] = v.x; dst[1] = v.y; dst[2] = v.z; dst[3] = v.w;
        }
        __syncthreads();

#pragma unroll 4
        for (int j = 0; j < 16; ++j) {
            const int k = kg + (j << 2);
            float s = 0.f;
#pragma unroll
            for (int d = 0; d < 64; d += 4) {
                float4 a = *(const float4*)&sQ[qi * SQ_STRIDE + d];
                float4 b = *(const float4*)&sKV[k * SQ_STRIDE + d];
                s = fmaf(a.x, b.x, s);
                s = fmaf(a.y, b.y, s);
                s = fmaf(a.z, b.z, s);
                s = fmaf(a.w, b.w, s);
            }
            const int kglob = (c << 6) + k;
            const int msk = pre_mask[((size_t)bs * NQ + qi) * NE + kglob];
            sS[qi * SS_STRIDE + kglob] = msk ? NEG_INF : s;
        }
    }
    __syncthreads();

    const int row = tid >> 2;
    const int part = tid & 3;
    const int kbeg = part << 6;

    float mx = NEG_INF;
    for (int k = 0; k < 64; ++k)
        mx = fmaxf(mx, sS[row * SS_STRIDE + kbeg + k]);
    sRed[(row << 2) + part] = mx;
    __syncthreads();
    const float rm = fmaxf(fmaxf(sRed[row << 2], sRed[(row << 2) + 1]),
                           fmaxf(sRed[(row << 2) + 2], sRed[(row << 2) + 3]));
    __syncthreads();

    const bool live = (rm != NEG_INF);
    float ssum = 0.f;
    for (int k = 0; k < 64; ++k) {
        const float v = sS[row * SS_STRIDE + kbeg + k];
        float e = 0.f;
        if (live && v != NEG_INF) e = __expf(v - rm);
        sS[row * SS_STRIDE + kbeg + k] = e;
        ssum += e;
    }
    sRed[(row << 2) + part] = ssum;
    __syncthreads();
    if (tid < 64) {
        const float t = sRed[tid << 2] + sRed[(tid << 2) + 1] +
                        sRed[(tid << 2) + 2] + sRed[(tid << 2) + 3];
        sInv[tid] = (t > 0.f) ? (1.f / t) : 0.f;
    }

    const int dg = tid & 3;
    float acc[16];
#pragma unroll
    for (int j = 0; j < 16; ++j) acc[j] = 0.f;

    for (int c = 0; c < 4; ++c) {
        __syncthreads();
#pragma unroll
        for (int it = 0; it < 4; ++it) {
            const int e = lq + (it << 4);
            float4 v = *(const float4*)(KV + ((size_t)bs * NE + (c << 6) + e) * (2 * EMBED_DIM)
                                        + EMBED_DIM + h * HEAD_DIM + ld4);
            float* dst = &sKV[e * SQ_STRIDE + ld4];
            dst[0] = v.x; dst[1] = v.y; dst[2] = v.z; dst[3] = v.w;
        }
        __syncthreads();

        for (int k = 0; k < 64; ++k) {
            const float w = sS[qi * SS_STRIDE + (c << 6) + k];
            const float* vp = &sKV[k * SQ_STRIDE + (dg << 4)];
            float4 v0 = *(const float4*)(vp);
            float4 v1 = *(const float4*)(vp + 4);
            float4 v2 = *(const float4*)(vp + 8);
            float4 v3 = *(const float4*)(vp + 12);
            acc[0]  = fmaf(w, v0.x, acc[0]);
            acc[1]  = fmaf(w, v0.y, acc[1]);
            acc[2]  = fmaf(w, v0.z, acc[2]);
            acc[3]  = fmaf(w, v0.w, acc[3]);
            acc[4]  = fmaf(w, v1.x, acc[4]);
            acc[5]  = fmaf(w, v1.y, acc[5]);
            acc[6]  = fmaf(w, v1.z, acc[6]);
            acc[7]  = fmaf(w, v1.w, acc[7]);
            acc[8]  = fmaf(w, v2.x, acc[8]);
            acc[9]  = fmaf(w, v2.y, acc[9]);
            acc[10] = fmaf(w, v2.z, acc[10]);
            acc[11] = fmaf(w, v2.w, acc[11]);
            acc[12] = fmaf(w, v3.x, acc[12]);
            acc[13] = fmaf(w, v3.y, acc[13]);
            acc[14] = fmaf(w, v3.z, acc[14]);
            acc[15] = fmaf(w, v3.w, acc[15]);
        }
    }

    const float inv = sInv[qi];
    float* op = ATTN + ((size_t)bs * NQ + qi) * EMBED_DIM + h * HEAD_DIM + (dg << 4);
#pragma unroll
    for (int j = 0; j < 16; j += 4) {
        float4 v;
        v.x = acc[j + 0] * inv;
        v.y = acc[j + 1] * inv;
        v.z = acc[j + 2] * inv;
        v.w = acc[j + 3] * inv;
        *(float4*)(op + j) = v;
    }
}

// ---------------------------------------------------------------------------
// kernel_launch
// ---------------------------------------------------------------------------
extern "C" void kernel_launch(void* const* d_in, const int* in_sizes, int n_in,
                              void* d_out, int out_size)
{
    const float* entities  = (const float*)d_in[0];
    const int*   pre_mask  = (const int*)d_in[1];
    const int*   post_mask = (const int*)d_in[2];
    const float* W_in      = (const float*)d_in[3];
    const float* W_out     = (const float*)d_in[4];
    const float* b_out     = (const float*)d_in[5];
    float* out = (float*)d_out;

    float *Qs, *KVs, *ATs;
    __nv_bfloat16 *eh, *el, *ah, *al, *wih, *wil, *woh, *wol;
    cudaGetSymbolAddress((void**)&Qs, g_Q);
    cudaGetSymbolAddress((void**)&KVs, g_KV);
    cudaGetSymbolAddress((void**)&ATs, g_ATTN);
    cudaGetSymbolAddress((void**)&eh, g_ent_hi);
    cudaGetSymbolAddress((void**)&el, g_ent_lo);
    cudaGetSymbolAddress((void**)&ah, g_attn_hi);
    cudaGetSymbolAddress((void**)&al, g_attn_lo);
    cudaGetSymbolAddress((void**)&wih, g_WinT_hi);
    cudaGetSymbolAddress((void**)&wil, g_WinT_lo);
    cudaGetSymbolAddress((void**)&woh, g_WoutT_hi);
    cudaGetSymbolAddress((void**)&wol, g_WoutT_lo);

    cudaFuncSetAttribute(gemm_bf16x3<0, false>,
                         cudaFuncAttributeMaxDynamicSharedMemorySize, GEMM_DYN_SMEM);
    cudaFuncSetAttribute(gemm_bf16x3<1, false>,
                         cudaFuncAttributeMaxDynamicSharedMemorySize, GEMM_DYN_SMEM);
    cudaFuncSetAttribute(gemm_bf16x3<0, true>,
                         cudaFuncAttributeMaxDynamicSharedMemorySize, GEMM_DYN_SMEM);
    cudaFuncSetAttribute(attn_kernel,
                         cudaFuncAttributeMaxDynamicSharedMemorySize, ATTN_SMEM_BYTES);

    // 1) split entities -> bf16 hi/lo
    {
        int n4 = (BS * NE * IN_DIM) / 4;
        split_kernel<<<(n4 + 255) / 256, 256>>>(entities, eh, el, n4);
    }
    // 2) split+transpose weights
    {
        int n = IN_DIM * QKV_DIM;
        splitT_kernel<<<(n + 255) / 256, 256>>>(W_in, wih, wil, IN_DIM, QKV_DIM);
        int n2 = EMBED_DIM * OUT_DIM;
        splitT_kernel<<<(n2 + 255) / 256, 256>>>(W_out, woh, wol, EMBED_DIM, OUT_DIM);
    }
    // 3) Q = entities[:, :64, :] @ W_in[:, 0:512]   (row gather)  M=32768, N=512
    gemm_bf16x3<1, false><<<dim3(EMBED_DIM / 128, (BS * NQ) / 128), 256, GEMM_DYN_SMEM>>>(
        eh, el, wih, wil, Qs, EMBED_DIM, nullptr, nullptr);

    // 4) KV = entities @ W_in[:, 512:1536]          M=131072, N=1024
    gemm_bf16x3<0, false><<<dim3((2 * EMBED_DIM) / 128, (BS * NE) / 128), 256, GEMM_DYN_SMEM>>>(
        eh, el, wih + (size_t)EMBED_DIM * IN_DIM, wil + (size_t)EMBED_DIM * IN_DIM,
        KVs, 2 * EMBED_DIM, nullptr, nullptr);

    // 5) attention
    attn_kernel<<<dim3(N_HEADS, BS), 256, ATTN_SMEM_BYTES>>>(Qs, KVs, pre_mask, ATs);

    // 6) split ATTN -> bf16 hi/lo
    {
        int n4 = (BS * NQ * EMBED_DIM) / 4;
        split_kernel<<<(n4 + 255) / 256, 256>>>(ATs, ah, al, n4);
    }
    // 7) out = ATTN @ W_out + b_out, post-masked    M=32768, N=512
    gemm_bf16x3<0, true><<<dim3(OUT_DIM / 128, (BS * NQ) / 128), 256, GEMM_DYN_SMEM>>>(
        ah, al, woh, wol, out, OUT_DIM, b_out, post_mask);
}

// round 4
// speedup vs baseline: 2.8420x; 1.5184x over previous
#include <cuda_runtime.h>
#include <cuda_bf16.h>
#include <math.h>
#include <stdint.h>

// Problem constants
#define BS 512
#define NE 256
#define NQ 64
#define IN_DIM 512
#define EMBED_DIM 512
#define OUT_DIM 512
#define N_HEADS 8
#define HEAD_DIM 64
#define QKV_DIM (3 * EMBED_DIM)

// Arch-feature gate: tcgen05 only exists in arch-specific (sm_103a/sm_100a) passes.
#if defined(__CUDA_ARCH__) && (defined(__CUDA_ARCH_FEAT_SM103_ALL) || defined(__CUDA_ARCH_FEAT_SM100_ALL) || defined(__CUDA_ARCH_FEAT_SM101_ALL))
#define HAS_TCGEN05 1
#else
#define HAS_TCGEN05 0
#endif

// ---------------------------------------------------------------------------
// Scratch (device globals: allocation-free rule)
// ---------------------------------------------------------------------------
__device__ float g_Q[(size_t)BS * NQ * EMBED_DIM];
__device__ float g_KV[(size_t)BS * NE * (2 * EMBED_DIM)];
__device__ float g_ATTN[(size_t)BS * NQ * EMBED_DIM];
__device__ __nv_bfloat16 g_ent_hi[(size_t)BS * NE * IN_DIM];
__device__ __nv_bfloat16 g_ent_lo[(size_t)BS * NE * IN_DIM];
__device__ __nv_bfloat16 g_attn_hi[(size_t)BS * NQ * EMBED_DIM];
__device__ __nv_bfloat16 g_attn_lo[(size_t)BS * NQ * EMBED_DIM];
__device__ __nv_bfloat16 g_WinT_hi[(size_t)QKV_DIM * IN_DIM];
__device__ __nv_bfloat16 g_WinT_lo[(size_t)QKV_DIM * IN_DIM];
__device__ __nv_bfloat16 g_WoutT_hi[(size_t)OUT_DIM * EMBED_DIM];
__device__ __nv_bfloat16 g_WoutT_lo[(size_t)OUT_DIM * EMBED_DIM];

// ---------------------------------------------------------------------------
// Common helpers (arch-neutral)
// ---------------------------------------------------------------------------
__device__ __forceinline__ uint32_t smem_u32(const void* p) {
    uint32_t a;
    asm("{ .reg .u64 t; cvta.to.shared.u64 t, %1; cvt.u32.u64 %0, t; }" : "=r"(a) : "l"(p));
    return a;
}
__device__ __forceinline__ void cp16(uint32_t s, const void* g) {
    asm volatile("cp.async.cg.shared.global [%0], [%1], 16;" :: "r"(s), "l"(g) : "memory");
}
__device__ __forceinline__ void ldsm4(uint32_t* r, uint32_t addr) {
    asm volatile("ldmatrix.sync.aligned.m8n8.x4.shared.b16 {%0,%1,%2,%3}, [%4];"
                 : "=r"(r[0]), "=r"(r[1]), "=r"(r[2]), "=r"(r[3]) : "r"(addr));
}
__device__ __forceinline__ void mma_bf16(float* d, const uint32_t* a, const uint32_t* b) {
    asm volatile("mma.sync.aligned.m16n8k16.row.col.f32.bf16.bf16.f32 "
                 "{%0,%1,%2,%3}, {%4,%5,%6,%7}, {%8,%9}, {%0,%1,%2,%3};"
                 : "+f"(d[0]), "+f"(d[1]), "+f"(d[2]), "+f"(d[3])
                 : "r"(a[0]), "r"(a[1]), "r"(a[2]), "r"(a[3]), "r"(b[0]), "r"(b[1]));
}

#if HAS_TCGEN05
// ---------------------------------------------------------------------------
// tcgen05 helpers (arch-specific pass only)
// ---------------------------------------------------------------------------
__device__ __forceinline__ uint32_t elect_one_pred() {
    uint32_t p;
    asm volatile("{\n\t.reg .pred p;\n\telect.sync _|p, 0xFFFFFFFF;\n\tselp.b32 %0, 1, 0, p;\n\t}" : "=r"(p));
    return p;
}
#define TCGEN05_ALLOC(sa, n) \
    asm volatile("tcgen05.alloc.cta_group::1.sync.aligned.shared::cta.b32 [%0], %1;" :: "r"((uint32_t)(sa)), "r"((uint32_t)(n)) : "memory")
#define TCGEN05_DEALLOC(t, n) \
    asm volatile("tcgen05.dealloc.cta_group::1.sync.aligned.b32 %0, %1;" :: "r"(t), "r"((uint32_t)(n)))
#define TCGEN05_RELINQ() \
    asm volatile("tcgen05.relinquish_alloc_permit.cta_group::1.sync.aligned;")
#define TCGEN05_COMMIT(mb) \
    asm volatile("tcgen05.commit.cta_group::1.mbarrier::arrive::one.shared::cluster.b64 [%0];" :: "r"((uint32_t)(mb)) : "memory")
#define TCGEN05_FENCE_AFTER() asm volatile("tcgen05.fence::after_thread_sync;" ::: "memory")
#define TCGEN05_FENCE_BEFORE() asm volatile("tcgen05.fence::before_thread_sync;" ::: "memory")
#define TCGEN05_WAIT_LD() asm volatile("tcgen05.wait::ld.sync.aligned;" ::: "memory")
#define FENCE_PROXY_ASYNC() asm volatile("fence.proxy.async;" ::: "memory")
#define MBARRIER_INIT(mb, cnt) \
    asm volatile("mbarrier.init.shared.b64 [%0], %1;" :: "r"((uint32_t)(mb)), "r"((uint32_t)(cnt)) : "memory")
#define MBARRIER_INVAL(mb) \
    asm volatile("mbarrier.inval.shared.b64 [%0];" :: "r"((uint32_t)(mb)) : "memory")
#define MBARRIER_WAIT_PARITY(mb, par) do {                                           \
    uint32_t _mb = (uint32_t)(mb); uint32_t _p = (uint32_t)(par); uint32_t _d;       \
    asm volatile("{\n\t.reg .pred p;\n\t"                                            \
        "mbarrier.try_wait.parity.acquire.cta.shared::cta.b64 p, [%1], %2;\n\t"      \
        "selp.b32 %0, 1, 0, p;\n\t}" : "=r"(_d) : "r"(_mb), "r"(_p) : "memory");     \
    if (!_d) {                                                                       \
        asm volatile("{\n\t.reg .pred P1;\n\t"                                       \
            "WL_%=:\n\t"                                                             \
            "mbarrier.try_wait.parity.acquire.cta.shared::cta.b64 P1, [%0], %1, 0x989680;\n\t" \
            "@P1 bra.uni WD_%=;\n\t"                                                 \
            "bra.uni WL_%=;\n\t"                                                     \
            "WD_%=:\n\t}" :: "r"(_mb), "r"(_p) : "memory");                          \
    }                                                                                \
} while (0)

#define TCGEN05_LD_32X32B_X32(r, ta) \
    asm volatile( \
        "tcgen05.ld.sync.aligned.32x32b.x32.b32 " \
        "{%0, %1, %2, %3, %4, %5, %6, %7, " \
        " %8, %9, %10, %11, %12, %13, %14, %15, " \
        " %16, %17, %18, %19, %20, %21, %22, %23, " \
        " %24, %25, %26, %27, %28, %29, %30, %31}, [%32];" \
        : "=r"((r)[0]),  "=r"((r)[1]),  "=r"((r)[2]),  "=r"((r)[3]), \
          "=r"((r)[4]),  "=r"((r)[5]),  "=r"((r)[6]),  "=r"((r)[7]), \
          "=r"((r)[8]),  "=r"((r)[9]),  "=r"((r)[10]), "=r"((r)[11]), \
          "=r"((r)[12]), "=r"((r)[13]), "=r"((r)[14]), "=r"((r)[15]), \
          "=r"((r)[16]), "=r"((r)[17]), "=r"((r)[18]), "=r"((r)[19]), \
          "=r"((r)[20]), "=r"((r)[21]), "=r"((r)[22]), "=r"((r)[23]), \
          "=r"((r)[24]), "=r"((r)[25]), "=r"((r)[26]), "=r"((r)[27]), \
          "=r"((r)[28]), "=r"((r)[29]), "=r"((r)[30]), "=r"((r)[31]) \
        : "r"(ta))

static constexpr uint64_t SMEM_DESC_BASE_SW128 =
    (uint64_t(2) << 61) | (uint64_t(1) << 46) | (uint64_t(64) << 32) | (uint64_t(1) << 16);
#define MAKE_SMEM_DESC(ba) (SMEM_DESC_BASE_SW128 | ((uint64_t)((ba) >> 4) & 0x3FFF))

__device__ __forceinline__ void mma_bf16_ss(uint32_t d, uint64_t da, uint64_t db,
                                            uint32_t idesc, bool en) {
    uint32_t e = en ? 1u : 0u;
    asm volatile(
        "{\n\t.reg .pred p;\n\t"
        "setp.ne.u32 p, %4, 0;\n\t"
        "tcgen05.mma.cta_group::1.kind::f16 [%0], %1, %2, %3, {%5, %5, %5, %5}, p;\n\t"
        "}"
        :: "r"(d), "l"(da), "l"(db), "r"(idesc), "r"(e), "r"(0u)
        : "memory");
}
// idesc: f32 accum, bf16 a, bf16 b, N=128, M=128
static constexpr uint32_t MMA_IDESC =
    (1u << 4) | (1u << 7) | (1u << 10) | ((128u / 8) << 17) | ((128u / 16) << 24);
#endif // HAS_TCGEN05

// ---------------------------------------------------------------------------
// bf16x3 GEMM (unchanged from Round 3 passing version)
// ---------------------------------------------------------------------------
#define GK 512
#define GKCHUNK 64
#define NCHUNKS 8
#define TILE_BYTES 16384
#define STAGE_BYTES (4 * TILE_BYTES)   // Ahi | Alo | Bhi | Blo
#define NSTAGES 3
#define GEMM_DYN_SMEM (NSTAGES * STAGE_BYTES + 1024)

template <int MODE, bool EPI>
__global__ void __launch_bounds__(256, 1)
gemm_bf16x3(const __nv_bfloat16* __restrict__ Ahi, const __nv_bfloat16* __restrict__ Alo,
            const __nv_bfloat16* __restrict__ Bhi, const __nv_bfloat16* __restrict__ Blo,
            float* __restrict__ C, int ldc,
            const float* __restrict__ bias, const int* __restrict__ post_mask)
{
    extern __shared__ char dyn_smem[];
    const int tid = threadIdx.x;
    const int wid = tid >> 5;
    const int lane = tid & 31;
    const int m0 = blockIdx.y << 7;
    const int n0 = blockIdx.x << 7;

    const uint32_t sbase = (smem_u32(dyn_smem) + 1023u) & ~1023u;

    auto issue_loads = [&](int ch, int st) {
        const uint32_t sb = sbase + st * STAGE_BYTES;
        const int koff = ch * GKCHUNK;
#pragma unroll
        for (int i = 0; i < 4; ++i) {
            const int idx = tid + (i << 8);
            const int row = idx >> 3;
            const int piece = idx & 7;
            const uint32_t off = (row << 7) + (piece << 4);
            const uint32_t sw = off ^ ((off >> 3) & 0x70);
            int grow = m0 + row;
            if (MODE == 1) grow = ((grow >> 6) << 8) | (grow & 63);
            const size_t gA = (size_t)grow * GK + koff + piece * 8;
            const size_t gB = (size_t)(n0 + row) * GK + koff + piece * 8;
            cp16(sb + sw, Ahi + gA);
            cp16(sb + TILE_BYTES + sw, Alo + gA);
            cp16(sb + 2 * TILE_BYTES + sw, Bhi + gB);
            cp16(sb + 3 * TILE_BYTES + sw, Blo + gB);
        }
        asm volatile("cp.async.commit_group;" ::: "memory");
    };

#if HAS_TCGEN05
    __shared__ uint32_t s_tmem_ptr[2];
    __shared__ __align__(8) uint64_t s_mbar[NSTAGES];

    if (wid == 0) {
        TCGEN05_ALLOC(smem_u32(s_tmem_ptr), 128);
        TCGEN05_RELINQ();
    }
    if (tid == 0) {
#pragma unroll
        for (int j = 0; j < NSTAGES; ++j) MBARRIER_INIT(smem_u32(&s_mbar[j]), 1);
    }
    __syncthreads();

    uint32_t tmem_base;
    asm volatile("ld.shared.b32 %0, [%1];" : "=r"(tmem_base) : "r"(smem_u32(s_tmem_ptr)));

    uint32_t mb_addr[NSTAGES];
#pragma unroll
    for (int j = 0; j < NSTAGES; ++j) mb_addr[j] = smem_u32(&s_mbar[j]);

    issue_loads(0, 0);
    issue_loads(1, 1);

    int ph[NSTAGES] = {0, 0, 0};

    for (int c = 0; c < NCHUNKS; ++c) {
        const int st = c % NSTAGES;
        if (c < NCHUNKS - 1) asm volatile("cp.async.wait_group 1;" ::: "memory");
        else                 asm volatile("cp.async.wait_group 0;" ::: "memory");
        __syncthreads();

        if (wid == 0) {
            if (elect_one_pred()) {
                FENCE_PROXY_ASYNC();
                const uint32_t sb = sbase + st * STAGE_BYTES;
                const uint64_t dAhi = MAKE_SMEM_DESC(sb);
                const uint64_t dAlo = MAKE_SMEM_DESC(sb + TILE_BYTES);
                const uint64_t dBhi = MAKE_SMEM_DESC(sb + 2 * TILE_BYTES);
                const uint64_t dBlo = MAKE_SMEM_DESC(sb + 3 * TILE_BYTES);
#pragma unroll
                for (int s = 0; s < 4; ++s) {
                    const bool first = (c == 0) && (s == 0);
                    mma_bf16_ss(tmem_base, dAhi + 2 * s, dBhi + 2 * s, MMA_IDESC, !first);
                    mma_bf16_ss(tmem_base, dAhi + 2 * s, dBlo + 2 * s, MMA_IDESC, true);
                    mma_bf16_ss(tmem_base, dAlo + 2 * s, dBhi + 2 * s, MMA_IDESC, true);
                }
                TCGEN05_COMMIT(mb_addr[st]);
            }
        }

        if (c >= 1) {
            const int w = (c - 1) % NSTAGES;
            MBARRIER_WAIT_PARITY(mb_addr[w], ph[w]);
            ph[w] ^= 1;
        }
        if (c + 2 < NCHUNKS) issue_loads(c + 2, (c + 2) % NSTAGES);
    }
    {
        const int w = (NCHUNKS - 1) % NSTAGES;
        MBARRIER_WAIT_PARITY(mb_addr[w], ph[w]);
        ph[w] ^= 1;
    }
    TCGEN05_FENCE_AFTER();

    {
        const int rsub = (wid & 3) << 5;
        const int colh = (wid >> 2) << 6;
        const int m = m0 + rsub + lane;
        bool zero = false;
        if (EPI) zero = (post_mask[m] != 0);
        float* crow = C + (size_t)m * ldc + n0;

#pragma unroll
        for (int half = 0; half < 2; ++half) {
            const int cbase = colh + half * 32;
            uint32_t r[32];
            TCGEN05_LD_32X32B_X32(r, tmem_base + cbase);
            TCGEN05_WAIT_LD();
#pragma unroll
            for (int j = 0; j < 32; j += 4) {
                float4 v;
                v.x = __uint_as_float(r[j + 0]);
                v.y = __uint_as_float(r[j + 1]);
                v.z = __uint_as_float(r[j + 2]);
                v.w = __uint_as_float(r[j + 3]);
                if (EPI) {
                    const int n = n0 + cbase + j;
                    v.x += bias[n + 0];
                    v.y += bias[n + 1];
                    v.z += bias[n + 2];
                    v.w += bias[n + 3];
                    if (zero) { v.x = 0.f; v.y = 0.f; v.z = 0.f; v.w = 0.f; }
                }
                *(float4*)(crow + cbase + j) = v;
            }
        }
        TCGEN05_FENCE_BEFORE();
    }

    __syncthreads();
    if (tid == 0) {
#pragma unroll
        for (int j = 0; j < NSTAGES; ++j) MBARRIER_INVAL(mb_addr[j]);
    }
    __syncthreads();
    if (wid == 0) TCGEN05_DEALLOC(tmem_base, 128);

#else
    // mma.sync fallback (unchanged)
    const int wm = (wid & 1) << 6;
    const int wn = (wid >> 1) << 5;

    float acc[4][4][4];
#pragma unroll
    for (int a = 0; a < 4; ++a)
#pragma unroll
        for (int b = 0; b < 4; ++b)
#pragma unroll
            for (int d = 0; d < 4; ++d) acc[a][b][d] = 0.f;

    issue_loads(0, 0);
    issue_loads(1, 1);

    for (int c = 0; c < NCHUNKS; ++c) {
        if (c < NCHUNKS - 1) asm volatile("cp.async.wait_group 1;" ::: "memory");
        else                 asm volatile("cp.async.wait_group 0;" ::: "memory");
        __syncthreads();
        const uint32_t sb = sbase + (c & 1) * STAGE_BYTES;

#pragma unroll
        for (int ks = 0; ks < 4; ++ks) {
            uint32_t ahi[4][4], alo[4][4];
#pragma unroll
            for (int mf = 0; mf < 4; ++mf) {
                const uint32_t row = wm + (mf << 4) + (lane & 15);
                const uint32_t kp = (ks << 1) + (lane >> 4);
                const uint32_t off = (row << 7) + (kp << 4);
                const uint32_t sw = off ^ ((off >> 3) & 0x70);
                ldsm4(ahi[mf], sb + sw);
                ldsm4(alo[mf], sb + TILE_BYTES + sw);
            }
            uint32_t bhi[4][2], blo[4][2];
#pragma unroll
            for (int nb = 0; nb < 2; ++nb) {
                const uint32_t row = wn + (nb << 4) + ((lane >> 4) << 3) + (lane & 7);
                const uint32_t kp = (ks << 1) + ((lane >> 3) & 1);
                const uint32_t off = (row << 7) + (kp << 4);
                const uint32_t sw = off ^ ((off >> 3) & 0x70);
                uint32_t t[4];
                ldsm4(t, sb + 2 * TILE_BYTES + sw);
                bhi[2 * nb][0] = t[0]; bhi[2 * nb][1] = t[1];
                bhi[2 * nb + 1][0] = t[2]; bhi[2 * nb + 1][1] = t[3];
                ldsm4(t, sb + 3 * TILE_BYTES + sw);
                blo[2 * nb][0] = t[0]; blo[2 * nb][1] = t[1];
                blo[2 * nb + 1][0] = t[2]; blo[2 * nb + 1][1] = t[3];
            }
#pragma unroll
            for (int mf = 0; mf < 4; ++mf)
#pragma unroll
                for (int nf = 0; nf < 4; ++nf) {
                    mma_bf16(acc[mf][nf], ahi[mf], bhi[nf]);
                    mma_bf16(acc[mf][nf], ahi[mf], blo[nf]);
                    mma_bf16(acc[mf][nf], alo[mf], bhi[nf]);
                }
        }
        __syncthreads();
        if (c + 2 < NCHUNKS) issue_loads(c + 2, (c + 2) & 1);
    }

#pragma unroll
    for (int mf = 0; mf < 4; ++mf) {
#pragma unroll
        for (int half = 0; half < 2; ++half) {
            const int m = m0 + wm + (mf << 4) + (half << 3) + (lane >> 2);
            bool zero = false;
            if (EPI) zero = (post_mask[m] != 0);
            float* crow = C + (size_t)m * ldc;
#pragma unroll
            for (int nf = 0; nf < 4; ++nf) {
                const int col = n0 + wn + (nf << 3) + ((lane & 3) << 1);
                float v0 = acc[mf][nf][half * 2 + 0];
                float v1 = acc[mf][nf][half * 2 + 1];
                if (EPI) {
                    v0 += bias[col];
                    v1 += bias[col + 1];
                    if (zero) { v0 = 0.f; v1 = 0.f; }
                }
                crow[col] = v0;
                crow[col + 1] = v1;
            }
        }
    }
#endif
}

// ---------------------------------------------------------------------------
// fp32 -> bf16 hi/lo split (vectorized)
// ---------------------------------------------------------------------------
__global__ void __launch_bounds__(256)
split_kernel(const float* __restrict__ in, __nv_bfloat16* __restrict__ hi,
             __nv_bfloat16* __restrict__ lo, int n4)
{
    int i = blockIdx.x * blockDim.x + threadIdx.x;
    if (i >= n4) return;
    float4 v = ((const float4*)in)[i];
    __nv_bfloat16 h0 = __float2bfloat16(v.x);
    __nv_bfloat16 h1 = __float2bfloat16(v.y);
    __nv_bfloat16 h2 = __float2bfloat16(v.z);
    __nv_bfloat16 h3 = __float2bfloat16(v.w);
    __nv_bfloat16 l0 = __float2bfloat16(v.x - __bfloat162float(h0));
    __nv_bfloat16 l1 = __float2bfloat16(v.y - __bfloat162float(h1));
    __nv_bfloat16 l2 = __float2bfloat16(v.z - __bfloat162float(h2));
    __nv_bfloat16 l3 = __float2bfloat16(v.w - __bfloat162float(h3));
    __nv_bfloat162 ph0; ph0.x = h0; ph0.y = h1;
    __nv_bfloat162 ph1; ph1.x = h2; ph1.y = h3;
    __nv_bfloat162 pl0; pl0.x = l0; pl0.y = l1;
    __nv_bfloat162 pl1; pl1.x = l2; pl1.y = l3;
    ((__nv_bfloat162*)hi)[2 * i + 0] = ph0;
    ((__nv_bfloat162*)hi)[2 * i + 1] = ph1;
    ((__nv_bfloat162*)lo)[2 * i + 0] = pl0;
    ((__nv_bfloat162*)lo)[2 * i + 1] = pl1;
}

// fp32 [K,N] -> bf16 hi/lo transposed [N,K]
__global__ void __launch_bounds__(256)
splitT_kernel(const float* __restrict__ in, __nv_bfloat16* __restrict__ hiT,
              __nv_bfloat16* __restrict__ loT, int Kd, int Nd)
{
    int i = blockIdx.x * blockDim.x + threadIdx.x;
    if (i >= Kd * Nd) return;
    int k = i / Nd, n = i % Nd;
    float x = in[i];
    __nv_bfloat16 h = __float2bfloat16(x);
    __nv_bfloat16 l = __float2bfloat16(x - __bfloat162float(h));
    hiT[(size_t)n * Kd + k] = h;
    loT[(size_t)n * Kd + k] = l;
}

// ---------------------------------------------------------------------------
// Attention v2: register-blocked, transposed P, rotation-swizzled K/V staging,
// mask folded into softmax (bitmask). One CTA per (head, batch), 256 threads.
//
// smem: sQ[64][68] | sKV[64][64] (rotated) | sPT[256][68] | sRed[256] | sInv[64]
// ---------------------------------------------------------------------------
#define AQ_STRIDE 68
#define APT_STRIDE 68
#define A_SQ 0
#define A_SKV (64 * AQ_STRIDE)
#define A_SPT (A_SKV + 64 * 64)
#define A_SRED (A_SPT + 256 * APT_STRIDE)
#define A_SINV (A_SRED + 256)
#define ATTN_SMEM_FLOATS (A_SINV + 64)
#define ATTN_SMEM_BYTES (ATTN_SMEM_FLOATS * 4)

__global__ void __launch_bounds__(256, 2)
attn_kernel(const float* __restrict__ Q,
            const float* __restrict__ KV,
            const int* __restrict__ pre_mask,
            float* __restrict__ ATTN)
{
    extern __shared__ float sm[];
    float* sQ  = sm + A_SQ;
    float* sKV = sm + A_SKV;
    float* sPT = sm + A_SPT;
    float* sRed = sm + A_SRED;
    float* sInv = sm + A_SINV;

    const int tid = threadIdx.x;
    const int h = blockIdx.x;
    const int bs = blockIdx.y;
    const float NEG_INF = -INFINITY;

    // ---- load Q tile (fold 1/8), 64 rows x 64 cols, stride 68 ----
    {
        const int lr = tid >> 4;           // 0..15
        const int lc = (tid & 15) << 2;    // 0..60
#pragma unroll
        for (int it = 0; it < 4; ++it) {
            const int qi = lr + (it << 4);
            float4 v = *(const float4*)(Q + ((size_t)bs * NQ + qi) * EMBED_DIM + h * HEAD_DIM + lc);
            float* dst = &sQ[qi * AQ_STRIDE + lc];
            dst[0] = v.x * 0.125f;
            dst[1] = v.y * 0.125f;
            dst[2] = v.z * 0.125f;
            dst[3] = v.w * 0.125f;
        }
    }

    // rotated-swizzle staging of one 64x64 chunk (K or V): float4 piece c of
    // row e stored at column group (c+e)&15.
    auto load_chunk = [&](const float* base) {
#pragma unroll
        for (int it = 0; it < 4; ++it) {
            const int idx = tid + (it << 8);
            const int e = idx >> 4;
            const int c = idx & 15;
            float4 v = *(const float4*)(base + (size_t)e * (2 * EMBED_DIM) + (c << 2));
            *(float4*)&sKV[(e << 6) + (((c + e) & 15) << 2)] = v;
        }
    };

    // ---- S = scaled Q @ K^T  -> sPT[k][q] (transposed, unmasked) ----
    // thread (qg = tid>>4, kt = tid&15): 4 q rows (qg*4..), 4 k rows {kt+16j}
    const int qg = tid >> 4;
    const int kt = tid & 15;

    for (int c4 = 0; c4 < 4; ++c4) {
        __syncthreads();   // previous chunk consumers done (first iter: Q stores)
        load_chunk(KV + ((size_t)bs * NE + (c4 << 6)) * (2 * EMBED_DIM) + h * HEAD_DIM);
        __syncthreads();

        float acc[4][4];
#pragma unroll
        for (int i = 0; i < 4; ++i)
#pragma unroll
            for (int j = 0; j < 4; ++j) acc[i][j] = 0.f;

#pragma unroll
        for (int d4 = 0; d4 < 16; ++d4) {
            float4 q4[4];
#pragma unroll
            for (int i = 0; i < 4; ++i)
                q4[i] = *(const float4*)&sQ[((qg << 2) + i) * AQ_STRIDE + (d4 << 2)];
#pragma unroll
            for (int j = 0; j < 4; ++j) {
                const int e = kt + (j << 4);
                float4 k4 = *(const float4*)&sKV[(e << 6) + (((d4 + e) & 15) << 2)];
#pragma unroll
                for (int i = 0; i < 4; ++i) {
                    acc[i][j] = fmaf(q4[i].x, k4.x, acc[i][j]);
                    acc[i][j] = fmaf(q4[i].y, k4.y, acc[i][j]);
                    acc[i][j] = fmaf(q4[i].z, k4.z, acc[i][j]);
                    acc[i][j] = fmaf(q4[i].w, k4.w, acc[i][j]);
                }
            }
        }
        // write S^T: for each of 4 k rows, contiguous float4 over q
#pragma unroll
        for (int j = 0; j < 4; ++j) {
            const int kglob = (c4 << 6) + kt + (j << 4);
            float4 v;
            v.x = acc[0][j]; v.y = acc[1][j]; v.z = acc[2][j]; v.w = acc[3][j];
            *(float4*)&sPT[kglob * APT_STRIDE + (qg << 2)] = v;
        }
    }
    __syncthreads();

    // ---- masked softmax over k (per q row; 4 threads/row), in-place on sPT ----
    {
        const int row = tid >> 2;        // q
        const int part = tid & 3;
        const int kbeg = part << 6;

        // pack 64 mask bits
        const int4* mrow = (const int4*)(pre_mask + ((size_t)bs * NQ + row) * NE + kbeg);
        uint64_t bits = 0;
#pragma unroll
        for (int g = 0; g < 16; ++g) {
            int4 m = mrow[g];
            uint64_t b = (uint64_t)(m.x != 0) | ((uint64_t)(m.y != 0) << 1) |
                         ((uint64_t)(m.z != 0) << 2) | ((uint64_t)(m.w != 0) << 3);
            bits |= b << (g << 2);
        }

        float mx = NEG_INF;
#pragma unroll 8
        for (int k = 0; k < 64; ++k) {
            if (!((bits >> k) & 1ull))
                mx = fmaxf(mx, sPT[(kbeg + k) * APT_STRIDE + row]);
        }
        sRed[(row << 2) + part] = mx;
        __syncthreads();
        const float rm = fmaxf(fmaxf(sRed[row << 2], sRed[(row << 2) + 1]),
                               fmaxf(sRed[(row << 2) + 2], sRed[(row << 2) + 3]));
        __syncthreads();

        const bool live = (rm != NEG_INF);
        float ssum = 0.f;
#pragma unroll 8
        for (int k = 0; k < 64; ++k) {
            float* p = &sPT[(kbeg + k) * APT_STRIDE + row];
            float e = 0.f;
            if (live && !((bits >> k) & 1ull)) e = __expf(*p - rm);
            *p = e;
            ssum += e;
        }
        sRed[(row << 2) + part] = ssum;
        __syncthreads();
        if (tid < 64) {
            const float t = sRed[tid << 2] + sRed[(tid << 2) + 1] +
                            sRed[(tid << 2) + 2] + sRed[(tid << 2) + 3];
            sInv[tid] = (t > 0.f) ? (1.f / t) : 0.f;
        }
    }

    // ---- A = P @ V : thread (qg2 = tid&15 -> 4 q, dg = tid>>4 -> 4 d) ----
    const int qg2 = tid & 15;
    const int dg = tid >> 4;

    float acc2[4][4];
#pragma unroll
    for (int i = 0; i < 4; ++i)
#pragma unroll
        for (int l = 0; l < 4; ++l) acc2[i][l] = 0.f;

    for (int c4 = 0; c4 < 4; ++c4) {
        __syncthreads();   // sKV free (and first iter: softmax writes visible)
        load_chunk(KV + ((size_t)bs * NE + (c4 << 6)) * (2 * EMBED_DIM) + EMBED_DIM + h * HEAD_DIM);
        __syncthreads();

#pragma unroll 4
        for (int e = 0; e < 64; ++e) {
            const int kglob = (c4 << 6) + e;
            float4 w4 = *(const float4*)&sPT[kglob * APT_STRIDE + (qg2 << 2)];
            float4 v4 = *(const float4*)&sKV[(e << 6) + ((((dg) + e) & 15) << 2)];
            acc2[0][0] = fmaf(w4.x, v4.x, acc2[0][0]);
            acc2[0][1] = fmaf(w4.x, v4.y, acc2[0][1]);
            acc2[0][2] = fmaf(w4.x, v4.z, acc2[0][2]);
            acc2[0][3] = fmaf(w4.x, v4.w, acc2[0][3]);
            acc2[1][0] = fmaf(w4.y, v4.x, acc2[1][0]);
            acc2[1][1] = fmaf(w4.y, v4.y, acc2[1][1]);
            acc2[1][2] = fmaf(w4.y, v4.z, acc2[1][2]);
            acc2[1][3] = fmaf(w4.y, v4.w, acc2[1][3]);
            acc2[2][0] = fmaf(w4.z, v4.x, acc2[2][0]);
            acc2[2][1] = fmaf(w4.z, v4.y, acc2[2][1]);
            acc2[2][2] = fmaf(w4.z, v4.z, acc2[2][2]);
            acc2[2][3] = fmaf(w4.z, v4.w, acc2[2][3]);
            acc2[3][0] = fmaf(w4.w, v4.x, acc2[3][0]);
            acc2[3][1] = fmaf(w4.w, v4.y, acc2[3][1]);
            acc2[3][2] = fmaf(w4.w, v4.z, acc2[3][2]);
            acc2[3][3] = fmaf(w4.w, v4.w, acc2[3][3]);
        }
    }

    // output: 4 q rows x 4 d cols, scaled by 1/sum
#pragma unroll
    for (int i = 0; i < 4; ++i) {
        const int qi = (qg2 << 2) + i;
        const float inv = sInv[qi];
        float4 v;
        v.x = acc2[i][0] * inv;
        v.y = acc2[i][1] * inv;
        v.z = acc2[i][2] * inv;
        v.w = acc2[i][3] * inv;
        *(float4*)(ATTN + ((size_t)bs * NQ + qi) * EMBED_DIM + h * HEAD_DIM + (dg << 2)) = v;
    }
}

// ---------------------------------------------------------------------------
// kernel_launch
// ---------------------------------------------------------------------------
extern "C" void kernel_launch(void* const* d_in, const int* in_sizes, int n_in,
                              void* d_out, int out_size)
{
    const float* entities  = (const float*)d_in[0];
    const int*   pre_mask  = (const int*)d_in[1];
    const int*   post_mask = (const int*)d_in[2];
    const float* W_in      = (const float*)d_in[3];
    const float* W_out     = (const float*)d_in[4];
    const float* b_out     = (const float*)d_in[5];
    float* out = (float*)d_out;

    float *Qs, *KVs, *ATs;
    __nv_bfloat16 *eh, *el, *ah, *al, *wih, *wil, *woh, *wol;
    cudaGetSymbolAddress((void**)&Qs, g_Q);
    cudaGetSymbolAddress((void**)&KVs, g_KV);
    cudaGetSymbolAddress((void**)&ATs, g_ATTN);
    cudaGetSymbolAddress((void**)&eh, g_ent_hi);
    cudaGetSymbolAddress((void**)&el, g_ent_lo);
    cudaGetSymbolAddress((void**)&ah, g_attn_hi);
    cudaGetSymbolAddress((void**)&al, g_attn_lo);
    cudaGetSymbolAddress((void**)&wih, g_WinT_hi);
    cudaGetSymbolAddress((void**)&wil, g_WinT_lo);
    cudaGetSymbolAddress((void**)&woh, g_WoutT_hi);
    cudaGetSymbolAddress((void**)&wol, g_WoutT_lo);

    cudaFuncSetAttribute(gemm_bf16x3<0, false>,
                         cudaFuncAttributeMaxDynamicSharedMemorySize, GEMM_DYN_SMEM);
    cudaFuncSetAttribute(gemm_bf16x3<1, false>,
                         cudaFuncAttributeMaxDynamicSharedMemorySize, GEMM_DYN_SMEM);
    cudaFuncSetAttribute(gemm_bf16x3<0, true>,
                         cudaFuncAttributeMaxDynamicSharedMemorySize, GEMM_DYN_SMEM);
    cudaFuncSetAttribute(attn_kernel,
                         cudaFuncAttributeMaxDynamicSharedMemorySize, ATTN_SMEM_BYTES);

    // 1) split entities -> bf16 hi/lo
    {
        int n4 = (BS * NE * IN_DIM) / 4;
        split_kernel<<<(n4 + 255) / 256, 256>>>(entities, eh, el, n4);
    }
    // 2) split+transpose weights
    {
        int n = IN_DIM * QKV_DIM;
        splitT_kernel<<<(n + 255) / 256, 256>>>(W_in, wih, wil, IN_DIM, QKV_DIM);
        int n2 = EMBED_DIM * OUT_DIM;
        splitT_kernel<<<(n2 + 255) / 256, 256>>>(W_out, woh, wol, EMBED_DIM, OUT_DIM);
    }
    // 3) Q = entities[:, :64, :] @ W_in[:, 0:512]   (row gather)
    gemm_bf16x3<1, false><<<dim3(EMBED_DIM / 128, (BS * NQ) / 128), 256, GEMM_DYN_SMEM>>>(
        eh, el, wih, wil, Qs, EMBED_DIM, nullptr, nullptr);

    // 4) KV = entities @ W_in[:, 512:1536]
    gemm_bf16x3<0, false><<<dim3((2 * EMBED_DIM) / 128, (BS * NE) / 128), 256, GEMM_DYN_SMEM>>>(
        eh, el, wih + (size_t)EMBED_DIM * IN_DIM, wil + (size_t)EMBED_DIM * IN_DIM,
        KVs, 2 * EMBED_DIM, nullptr, nullptr);

    // 5) attention
    attn_kernel<<<dim3(N_HEADS, BS), 256, ATTN_SMEM_BYTES>>>(Qs, KVs, pre_mask, ATs);

    // 6) split ATTN -> bf16 hi/lo
    {
        int n4 = (BS * NQ * EMBED_DIM) / 4;
        split_kernel<<<(n4 + 255) / 256, 256>>>(ATs, ah, al, n4);
    }
    // 7) out = ATTN @ W_out + b_out, post-masked
    gemm_bf16x3<0, true><<<dim3(OUT_DIM / 128, (BS * NQ) / 128), 256, GEMM_DYN_SMEM>>>(
        ah, al, woh, wol, out, OUT_DIM, b_out, post_mask);
}

// round 5
// speedup vs baseline: 3.9104x; 1.3759x over previous
#include <cuda_runtime.h>
#include <cuda_bf16.h>
#include <math.h>
#include <stdint.h>

// Problem constants
#define BS 512
#define NE 256
#define NQ 64
#define IN_DIM 512
#define EMBED_DIM 512
#define OUT_DIM 512
#define N_HEADS 8
#define HEAD_DIM 64
#define QKV_DIM (3 * EMBED_DIM)

// Arch-feature gate: tcgen05 only exists in arch-specific (sm_103a/sm_100a) passes.
#if defined(__CUDA_ARCH__) && (defined(__CUDA_ARCH_FEAT_SM103_ALL) || defined(__CUDA_ARCH_FEAT_SM100_ALL) || defined(__CUDA_ARCH_FEAT_SM101_ALL))
#define HAS_TCGEN05 1
#else
#define HAS_TCGEN05 0
#endif

// ---------------------------------------------------------------------------
// Scratch (device globals). All GEMM operands live in TILE-CONTIGUOUS,
// PRE-SWIZZLED (SW128) layout: [M/128 panels][8 K-chunks][16384 bytes].
// ---------------------------------------------------------------------------
__device__ float g_Q[(size_t)BS * NQ * EMBED_DIM];
__device__ float g_KV[(size_t)BS * NE * (2 * EMBED_DIM)];
__device__ float g_ATTN[(size_t)BS * NQ * EMBED_DIM];
__device__ __align__(1024) __nv_bfloat16 g_ent_hi[(size_t)BS * NE * IN_DIM];
__device__ __align__(1024) __nv_bfloat16 g_ent_lo[(size_t)BS * NE * IN_DIM];
__device__ __align__(1024) __nv_bfloat16 g_q_hi[(size_t)BS * NQ * IN_DIM];
__device__ __align__(1024) __nv_bfloat16 g_q_lo[(size_t)BS * NQ * IN_DIM];
__device__ __align__(1024) __nv_bfloat16 g_attn_hi[(size_t)BS * NQ * EMBED_DIM];
__device__ __align__(1024) __nv_bfloat16 g_attn_lo[(size_t)BS * NQ * EMBED_DIM];
__device__ __align__(1024) __nv_bfloat16 g_WinT_hi[(size_t)QKV_DIM * IN_DIM];
__device__ __align__(1024) __nv_bfloat16 g_WinT_lo[(size_t)QKV_DIM * IN_DIM];
__device__ __align__(1024) __nv_bfloat16 g_WoutT_hi[(size_t)OUT_DIM * EMBED_DIM];
__device__ __align__(1024) __nv_bfloat16 g_WoutT_lo[(size_t)OUT_DIM * EMBED_DIM];

// ---------------------------------------------------------------------------
// Common helpers
// ---------------------------------------------------------------------------
__device__ __forceinline__ uint32_t smem_u32(const void* p) {
    uint32_t a;
    asm("{ .reg .u64 t; cvta.to.shared.u64 t, %1; cvt.u32.u64 %0, t; }" : "=r"(a) : "l"(p));
    return a;
}
__device__ __forceinline__ void cp16(uint32_t s, const void* g) {
    asm volatile("cp.async.cg.shared.global [%0], [%1], 16;" :: "r"(s), "l"(g) : "memory");
}
__device__ __forceinline__ void ldsm4(uint32_t* r, uint32_t addr) {
    asm volatile("ldmatrix.sync.aligned.m8n8.x4.shared.b16 {%0,%1,%2,%3}, [%4];"
                 : "=r"(r[0]), "=r"(r[1]), "=r"(r[2]), "=r"(r[3]) : "r"(addr));
}
__device__ __forceinline__ void mma_bf16(float* d, const uint32_t* a, const uint32_t* b) {
    asm volatile("mma.sync.aligned.m16n8k16.row.col.f32.bf16.bf16.f32 "
                 "{%0,%1,%2,%3}, {%4,%5,%6,%7}, {%8,%9}, {%0,%1,%2,%3};"
                 : "+f"(d[0]), "+f"(d[1]), "+f"(d[2]), "+f"(d[3])
                 : "r"(a[0]), "r"(a[1]), "r"(a[2]), "r"(a[3]), "r"(b[0]), "r"(b[1]));
}

#if HAS_TCGEN05
// ---------------------------------------------------------------------------
// tcgen05 + bulk-async helpers (arch-specific pass only)
// ---------------------------------------------------------------------------
__device__ __forceinline__ uint32_t elect_one_pred() {
    uint32_t p;
    asm volatile("{\n\t.reg .pred p;\n\telect.sync _|p, 0xFFFFFFFF;\n\tselp.b32 %0, 1, 0, p;\n\t}" : "=r"(p));
    return p;
}
#define TCGEN05_ALLOC(sa, n) \
    asm volatile("tcgen05.alloc.cta_group::1.sync.aligned.shared::cta.b32 [%0], %1;" :: "r"((uint32_t)(sa)), "r"((uint32_t)(n)) : "memory")
#define TCGEN05_DEALLOC(t, n) \
    asm volatile("tcgen05.dealloc.cta_group::1.sync.aligned.b32 %0, %1;" :: "r"(t), "r"((uint32_t)(n)))
#define TCGEN05_RELINQ() \
    asm volatile("tcgen05.relinquish_alloc_permit.cta_group::1.sync.aligned;")
#define TCGEN05_COMMIT(mb) \
    asm volatile("tcgen05.commit.cta_group::1.mbarrier::arrive::one.shared::cluster.b64 [%0];" :: "r"((uint32_t)(mb)) : "memory")
#define TCGEN05_FENCE_AFTER() asm volatile("tcgen05.fence::after_thread_sync;" ::: "memory")
#define TCGEN05_FENCE_BEFORE() asm volatile("tcgen05.fence::before_thread_sync;" ::: "memory")
#define TCGEN05_WAIT_LD() asm volatile("tcgen05.wait::ld.sync.aligned;" ::: "memory")
#define MBARRIER_INIT(mb, cnt) \
    asm volatile("mbarrier.init.shared.b64 [%0], %1;" :: "r"((uint32_t)(mb)), "r"((uint32_t)(cnt)) : "memory")
#define MBARRIER_INVAL(mb) \
    asm volatile("mbarrier.inval.shared.b64 [%0];" :: "r"((uint32_t)(mb)) : "memory")
#define MBARRIER_EXPECT_TX(mb, tx) \
    asm volatile("mbarrier.arrive.expect_tx.shared.b64 _, [%0], %1;" :: "r"((uint32_t)(mb)), "r"((uint32_t)(tx)) : "memory")
#define MBARRIER_WAIT_PARITY(mb, par) do {                                           \
    uint32_t _mb = (uint32_t)(mb); uint32_t _p = (uint32_t)(par); uint32_t _d;       \
    asm volatile("{\n\t.reg .pred p;\n\t"                                            \
        "mbarrier.try_wait.parity.acquire.cta.shared::cta.b64 p, [%1], %2;\n\t"      \
        "selp.b32 %0, 1, 0, p;\n\t}" : "=r"(_d) : "r"(_mb), "r"(_p) : "memory");     \
    if (!_d) {                                                                       \
        asm volatile("{\n\t.reg .pred P1;\n\t"                                       \
            "WL_%=:\n\t"                                                             \
            "mbarrier.try_wait.parity.acquire.cta.shared::cta.b64 P1, [%0], %1, 0x989680;\n\t" \
            "@P1 bra.uni WD_%=;\n\t"                                                 \
            "bra.uni WL_%=;\n\t"                                                     \
            "WD_%=:\n\t}" :: "r"(_mb), "r"(_p) : "memory");                          \
    }                                                                                \
} while (0)

// contiguous bulk copy gmem -> smem with mbarrier completion
__device__ __forceinline__ void cp_bulk(uint32_t dst, const void* src, uint32_t bytes, uint32_t mb) {
    asm volatile("cp.async.bulk.shared::cta.global.mbarrier::complete_tx::bytes [%0], [%1], %2, [%3];"
                 :: "r"(dst), "l"(src), "r"(bytes), "r"(mb) : "memory");
}

#define TCGEN05_LD_32X32B_X32(r, ta) \
    asm volatile( \
        "tcgen05.ld.sync.aligned.32x32b.x32.b32 " \
        "{%0, %1, %2, %3, %4, %5, %6, %7, " \
        " %8, %9, %10, %11, %12, %13, %14, %15, " \
        " %16, %17, %18, %19, %20, %21, %22, %23, " \
        " %24, %25, %26, %27, %28, %29, %30, %31}, [%32];" \
        : "=r"((r)[0]),  "=r"((r)[1]),  "=r"((r)[2]),  "=r"((r)[3]), \
          "=r"((r)[4]),  "=r"((r)[5]),  "=r"((r)[6]),  "=r"((r)[7]), \
          "=r"((r)[8]),  "=r"((r)[9]),  "=r"((r)[10]), "=r"((r)[11]), \
          "=r"((r)[12]), "=r"((r)[13]), "=r"((r)[14]), "=r"((r)[15]), \
          "=r"((r)[16]), "=r"((r)[17]), "=r"((r)[18]), "=r"((r)[19]), \
          "=r"((r)[20]), "=r"((r)[21]), "=r"((r)[22]), "=r"((r)[23]), \
          "=r"((r)[24]), "=r"((r)[25]), "=r"((r)[26]), "=r"((r)[27]), \
          "=r"((r)[28]), "=r"((r)[29]), "=r"((r)[30]), "=r"((r)[31]) \
        : "r"(ta))

static constexpr uint64_t SMEM_DESC_BASE_SW128 =
    (uint64_t(2) << 61) | (uint64_t(1) << 46) | (uint64_t(64) << 32) | (uint64_t(1) << 16);
#define MAKE_SMEM_DESC(ba) (SMEM_DESC_BASE_SW128 | ((uint64_t)((ba) >> 4) & 0x3FFF))

__device__ __forceinline__ void mma_bf16_ss(uint32_t d, uint64_t da, uint64_t db,
                                            uint32_t idesc, bool en) {
    uint32_t e = en ? 1u : 0u;
    asm volatile(
        "{\n\t.reg .pred p;\n\t"
        "setp.ne.u32 p, %4, 0;\n\t"
        "tcgen05.mma.cta_group::1.kind::f16 [%0], %1, %2, %3, {%5, %5, %5, %5}, p;\n\t"
        "}"
        :: "r"(d), "l"(da), "l"(db), "r"(idesc), "r"(e), "r"(0u)
        : "memory");
}
// idesc: f32 accum, bf16 a, bf16 b, N=128, M=128
static constexpr uint32_t MMA_IDESC =
    (1u << 4) | (1u << 7) | (1u << 10) | ((128u / 8) << 17) | ((128u / 16) << 24);
#endif // HAS_TCGEN05

// ---------------------------------------------------------------------------
// bf16x3 GEMM v2: operands are tile-contiguous pre-swizzled.
// tcgen05 path: single elected thread drives bulk-async + MMA pipeline,
// fully mbarrier-based (no per-chunk syncthreads). Other threads wait "done".
// ---------------------------------------------------------------------------
#define GK 512
#define NCHUNKS 8
#define TILE_BYTES 16384
#define STAGE_BYTES (4 * TILE_BYTES)   // Ahi | Alo | Bhi | Blo
#define NSTAGES 3
#define GEMM_DYN_SMEM (NSTAGES * STAGE_BYTES + 1024)

template <bool EPI>
__global__ void __launch_bounds__(256, 1)
gemm_bf16x3(const __nv_bfloat16* __restrict__ Ahi, const __nv_bfloat16* __restrict__ Alo,
            const __nv_bfloat16* __restrict__ Bhi, const __nv_bfloat16* __restrict__ Blo,
            float* __restrict__ C, int ldc,
            const float* __restrict__ bias, const int* __restrict__ post_mask)
{
    extern __shared__ char dyn_smem[];
    const int tid = threadIdx.x;
    const int wid = tid >> 5;
    const int lane = tid & 31;
    const int m0 = blockIdx.y << 7;
    const int n0 = blockIdx.x << 7;
    const int pm = blockIdx.y;          // A panel
    const int pn = blockIdx.x;          // B panel

    const uint32_t sbase = (smem_u32(dyn_smem) + 1023u) & ~1023u;

#if HAS_TCGEN05
    __shared__ uint32_t s_tmem_ptr[2];
    __shared__ __align__(8) uint64_t s_full[NSTAGES];
    __shared__ __align__(8) uint64_t s_empty[NSTAGES];
    __shared__ __align__(8) uint64_t s_done;

    if (wid == 0) {
        TCGEN05_ALLOC(smem_u32(s_tmem_ptr), 128);
        TCGEN05_RELINQ();
    }
    if (tid == 0) {
#pragma unroll
        for (int j = 0; j < NSTAGES; ++j) {
            MBARRIER_INIT(smem_u32(&s_full[j]), 1);
            MBARRIER_INIT(smem_u32(&s_empty[j]), 1);
        }
        MBARRIER_INIT(smem_u32(&s_done), 1);
    }
    __syncthreads();

    uint32_t tmem_base;
    asm volatile("ld.shared.b32 %0, [%1];" : "=r"(tmem_base) : "r"(smem_u32(s_tmem_ptr)));

    if (wid == 0 && elect_one_pred()) {
        uint32_t fa[NSTAGES], ea[NSTAGES];
#pragma unroll
        for (int j = 0; j < NSTAGES; ++j) {
            fa[j] = smem_u32(&s_full[j]);
            ea[j] = smem_u32(&s_empty[j]);
        }
        const char* pAhi = (const char*)Ahi + (size_t)pm * (8 * TILE_BYTES);
        const char* pAlo = (const char*)Alo + (size_t)pm * (8 * TILE_BYTES);
        const char* pBhi = (const char*)Bhi + (size_t)pn * (8 * TILE_BYTES);
        const char* pBlo = (const char*)Blo + (size_t)pn * (8 * TILE_BYTES);

        auto load_chunk = [&](int ch, int st) {
            const uint32_t sb = sbase + st * STAGE_BYTES;
            const uint32_t mb = fa[st];
            MBARRIER_EXPECT_TX(mb, STAGE_BYTES);
            const size_t o = (size_t)ch * TILE_BYTES;
            cp_bulk(sb,                  pAhi + o, TILE_BYTES, mb);
            cp_bulk(sb + TILE_BYTES,     pAlo + o, TILE_BYTES, mb);
            cp_bulk(sb + 2 * TILE_BYTES, pBhi + o, TILE_BYTES, mb);
            cp_bulk(sb + 3 * TILE_BYTES, pBlo + o, TILE_BYTES, mb);
        };

        load_chunk(0, 0);
        load_chunk(1, 1);
        load_chunk(2, 2);

        int fph[NSTAGES] = {0, 0, 0};
        int eph[NSTAGES] = {0, 0, 0};

        for (int c = 0; c < NCHUNKS; ++c) {
            const int st = c % NSTAGES;
            MBARRIER_WAIT_PARITY(fa[st], fph[st]);
            fph[st] ^= 1;

            const uint32_t sb = sbase + st * STAGE_BYTES;
            const uint64_t dAhi = MAKE_SMEM_DESC(sb);
            const uint64_t dAlo = MAKE_SMEM_DESC(sb + TILE_BYTES);
            const uint64_t dBhi = MAKE_SMEM_DESC(sb + 2 * TILE_BYTES);
            const uint64_t dBlo = MAKE_SMEM_DESC(sb + 3 * TILE_BYTES);
#pragma unroll
            for (int s = 0; s < 4; ++s) {
                const bool first = (c == 0) && (s == 0);
                mma_bf16_ss(tmem_base, dAhi + 2 * s, dBhi + 2 * s, MMA_IDESC, !first);
                mma_bf16_ss(tmem_base, dAhi + 2 * s, dBlo + 2 * s, MMA_IDESC, true);
                mma_bf16_ss(tmem_base, dAlo + 2 * s, dBhi + 2 * s, MMA_IDESC, true);
            }
            if (c + NSTAGES < NCHUNKS) {
                TCGEN05_COMMIT(ea[st]);                  // this chunk's MMAs done -> stage free
                MBARRIER_WAIT_PARITY(ea[st], eph[st]);
                eph[st] ^= 1;
                load_chunk(c + NSTAGES, st);
            } else if (c == NCHUNKS - 1) {
                TCGEN05_COMMIT(smem_u32(&s_done));       // tracks all remaining MMAs
            }
        }
    }

    // all 256 threads wait for all MMAs to complete
    MBARRIER_WAIT_PARITY(smem_u32(&s_done), 0);
    TCGEN05_FENCE_AFTER();

    // epilogue: warp (wid&3) -> 32-row subpartition, (wid>>2) -> column half
    {
        const int rsub = (wid & 3) << 5;
        const int colh = (wid >> 2) << 6;
        const int m = m0 + rsub + lane;
        bool zero = false;
        if (EPI) zero = (post_mask[m] != 0);
        float* crow = C + (size_t)m * ldc + n0;

#pragma unroll
        for (int half = 0; half < 2; ++half) {
            const int cbase = colh + half * 32;
            uint32_t r[32];
            TCGEN05_LD_32X32B_X32(r, tmem_base + cbase);
            TCGEN05_WAIT_LD();
#pragma unroll
            for (int j = 0; j < 32; j += 4) {
                float4 v;
                v.x = __uint_as_float(r[j + 0]);
                v.y = __uint_as_float(r[j + 1]);
                v.z = __uint_as_float(r[j + 2]);
                v.w = __uint_as_float(r[j + 3]);
                if (EPI) {
                    const int n = n0 + cbase + j;
                    v.x += bias[n + 0];
                    v.y += bias[n + 1];
                    v.z += bias[n + 2];
                    v.w += bias[n + 3];
                    if (zero) { v.x = 0.f; v.y = 0.f; v.z = 0.f; v.w = 0.f; }
                }
                *(float4*)(crow + cbase + j) = v;
            }
        }
        TCGEN05_FENCE_BEFORE();
    }

    __syncthreads();
    if (tid == 0) {
#pragma unroll
        for (int j = 0; j < NSTAGES; ++j) {
            MBARRIER_INVAL(smem_u32(&s_full[j]));
            MBARRIER_INVAL(smem_u32(&s_empty[j]));
        }
        MBARRIER_INVAL(smem_u32(&s_done));
    }
    __syncthreads();
    if (wid == 0) TCGEN05_DEALLOC(tmem_base, 128);

#else
    // =========================== mma.sync fallback ==========================
    // Tiled layout in gmem is already swizzled; loads are identity copies.
    const int wm = (wid & 1) << 6;
    const int wn = (wid >> 1) << 5;

    auto issue_loads = [&](int ch, int st) {
        const uint32_t sb = sbase + st * STAGE_BYTES;
        const char* pA0 = (const char*)Ahi + ((size_t)pm * 8 + ch) * TILE_BYTES;
        const char* pA1 = (const char*)Alo + ((size_t)pm * 8 + ch) * TILE_BYTES;
        const char* pB0 = (const char*)Bhi + ((size_t)pn * 8 + ch) * TILE_BYTES;
        const char* pB1 = (const char*)Blo + ((size_t)pn * 8 + ch) * TILE_BYTES;
#pragma unroll
        for (int i = 0; i < 4; ++i) {
            const uint32_t u = (tid + (i << 8)) << 4;   // 0..16368
            cp16(sb + u, pA0 + u);
            cp16(sb + TILE_BYTES + u, pA1 + u);
            cp16(sb + 2 * TILE_BYTES + u, pB0 + u);
            cp16(sb + 3 * TILE_BYTES + u, pB1 + u);
        }
        asm volatile("cp.async.commit_group;" ::: "memory");
    };

    float acc[4][4][4];
#pragma unroll
    for (int a = 0; a < 4; ++a)
#pragma unroll
        for (int b = 0; b < 4; ++b)
#pragma unroll
            for (int d = 0; d < 4; ++d) acc[a][b][d] = 0.f;

    issue_loads(0, 0);
    issue_loads(1, 1);

    for (int c = 0; c < NCHUNKS; ++c) {
        if (c < NCHUNKS - 1) asm volatile("cp.async.wait_group 1;" ::: "memory");
        else                 asm volatile("cp.async.wait_group 0;" ::: "memory");
        __syncthreads();
        const uint32_t sb = sbase + (c & 1) * STAGE_BYTES;

#pragma unroll
        for (int ks = 0; ks < 4; ++ks) {
            uint32_t ahi[4][4], alo[4][4];
#pragma unroll
            for (int mf = 0; mf < 4; ++mf) {
                const uint32_t row = wm + (mf << 4) + (lane & 15);
                const uint32_t kp = (ks << 1) + (lane >> 4);
                const uint32_t off = (row << 7) + (kp << 4);
                const uint32_t sw = off ^ ((off >> 3) & 0x70);
                ldsm4(ahi[mf], sb + sw);
                ldsm4(alo[mf], sb + TILE_BYTES + sw);
            }
            uint32_t bhi[4][2], blo[4][2];
#pragma unroll
            for (int nb = 0; nb < 2; ++nb) {
                const uint32_t row = wn + (nb << 4) + ((lane >> 4) << 3) + (lane & 7);
                const uint32_t kp = (ks << 1) + ((lane >> 3) & 1);
                const uint32_t off = (row << 7) + (kp << 4);
                const uint32_t sw = off ^ ((off >> 3) & 0x70);
                uint32_t t[4];
                ldsm4(t, sb + 2 * TILE_BYTES + sw);
                bhi[2 * nb][0] = t[0]; bhi[2 * nb][1] = t[1];
                bhi[2 * nb + 1][0] = t[2]; bhi[2 * nb + 1][1] = t[3];
                ldsm4(t, sb + 3 * TILE_BYTES + sw);
                blo[2 * nb][0] = t[0]; blo[2 * nb][1] = t[1];
                blo[2 * nb + 1][0] = t[2]; blo[2 * nb + 1][1] = t[3];
            }
#pragma unroll
            for (int mf = 0; mf < 4; ++mf)
#pragma unroll
                for (int nf = 0; nf < 4; ++nf) {
                    mma_bf16(acc[mf][nf], ahi[mf], bhi[nf]);
                    mma_bf16(acc[mf][nf], ahi[mf], blo[nf]);
                    mma_bf16(acc[mf][nf], alo[mf], bhi[nf]);
                }
        }
        __syncthreads();
        if (c + 2 < NCHUNKS) issue_loads(c + 2, (c + 2) & 1);
    }

#pragma unroll
    for (int mf = 0; mf < 4; ++mf) {
#pragma unroll
        for (int half = 0; half < 2; ++half) {
            const int m = m0 + wm + (mf << 4) + (half << 3) + (lane >> 2);
            bool zero = false;
            if (EPI) zero = (post_mask[m] != 0);
            float* crow = C + (size_t)m * ldc;
#pragma unroll
            for (int nf = 0; nf < 4; ++nf) {
                const int col = n0 + wn + (nf << 3) + ((lane & 3) << 1);
                float v0 = acc[mf][nf][half * 2 + 0];
                float v1 = acc[mf][nf][half * 2 + 1];
                if (EPI) {
                    v0 += bias[col];
                    v1 += bias[col + 1];
                    if (zero) { v0 = 0.f; v1 = 0.f; }
                }
                crow[col] = v0;
                crow[col + 1] = v1;
            }
        }
    }
#endif
}

// ---------------------------------------------------------------------------
// Splits: fp32 -> bf16 hi/lo into TILED+SWIZZLED layout.
// One thread handles 8 consecutive K of one row (one 16B unit per buffer).
// ---------------------------------------------------------------------------
__device__ __forceinline__ void pack8(const float* src, uint4& hv, uint4& lv) {
    float x[8];
#pragma unroll
    for (int j = 0; j < 8; ++j) x[j] = src[j];
    __nv_bfloat16 hb[8], lb[8];
#pragma unroll
    for (int j = 0; j < 8; ++j) {
        hb[j] = __float2bfloat16(x[j]);
        lb[j] = __float2bfloat16(x[j] - __bfloat162float(hb[j]));
    }
    uint32_t* hp = (uint32_t*)&hv;
    uint32_t* lp = (uint32_t*)&lv;
#pragma unroll
    for (int j = 0; j < 4; ++j) {
        __nv_bfloat162 h2; h2.x = hb[2 * j]; h2.y = hb[2 * j + 1];
        __nv_bfloat162 l2; l2.x = lb[2 * j]; l2.y = lb[2 * j + 1];
        hp[j] = *(uint32_t*)&h2;
        lp[j] = *(uint32_t*)&l2;
    }
}

__device__ __forceinline__ size_t tiled_off(int m, int k) {
    const int panel = m >> 7, r = m & 127, ch = k >> 6;
    uint32_t off = (uint32_t)(r << 7) + ((k & 63) << 1);
    off = off ^ ((off >> 3) & 0x70);
    return ((size_t)(panel * 8 + ch) << 14) + off;
}

// A-type: src [Mtot, 512] row-major; optionally extract compact Q rows.
__global__ void __launch_bounds__(256)
split_tiledA(const float* __restrict__ in, __nv_bfloat16* __restrict__ hi,
             __nv_bfloat16* __restrict__ lo, __nv_bfloat16* __restrict__ qhi,
             __nv_bfloat16* __restrict__ qlo, int Mtot, int withQ)
{
    int i = blockIdx.x * blockDim.x + threadIdx.x;
    const int units = Mtot << 6;               // Mtot * 512 / 8
    if (i >= units) return;
    const int m = i >> 6;
    const int k = (i & 63) << 3;

    uint4 hv, lv;
    pack8(in + (size_t)m * GK + k, hv, lv);

    const size_t o = tiled_off(m, k);
    *(uint4*)((char*)hi + o) = hv;
    *(uint4*)((char*)lo + o) = lv;

    if (withQ && (m & 255) < 64) {
        const int mq = ((m >> 8) << 6) + (m & 63);
        const size_t oq = tiled_off(mq, k);
        *(uint4*)((char*)qhi + oq) = hv;
        *(uint4*)((char*)qlo + oq) = lv;
    }
}

// W-type: src [512, Nd] row-major -> transposed tiled [Nd rows, 512 K]
__global__ void __launch_bounds__(256)
splitT_tiled(const float* __restrict__ in, __nv_bfloat16* __restrict__ hiT,
             __nv_bfloat16* __restrict__ loT, int Nd)
{
    int i = blockIdx.x * blockDim.x + threadIdx.x;
    const int units = Nd << 6;
    if (i >= units) return;
    const int n = i >> 6;
    const int k = (i & 63) << 3;

    float x[8];
#pragma unroll
    for (int j = 0; j < 8; ++j) x[j] = in[(size_t)(k + j) * Nd + n];
    uint4 hv, lv;
    pack8(x, hv, lv);

    const size_t o = tiled_off(n, k);
    *(uint4*)((char*)hiT + o) = hv;
    *(uint4*)((char*)loT + o) = lv;
}

// ---------------------------------------------------------------------------
// Attention (Round-4 proven version, unchanged)
// ---------------------------------------------------------------------------
#define AQ_STRIDE 68
#define APT_STRIDE 68
#define A_SQ 0
#define A_SKV (64 * AQ_STRIDE)
#define A_SPT (A_SKV + 64 * 64)
#define A_SRED (A_SPT + 256 * APT_STRIDE)
#define A_SINV (A_SRED + 256)
#define ATTN_SMEM_FLOATS (A_SINV + 64)
#define ATTN_SMEM_BYTES (ATTN_SMEM_FLOATS * 4)

__global__ void __launch_bounds__(256, 2)
attn_kernel(const float* __restrict__ Q,
            const float* __restrict__ KV,
            const int* __restrict__ pre_mask,
            float* __restrict__ ATTN)
{
    extern __shared__ float sm[];
    float* sQ  = sm + A_SQ;
    float* sKV = sm + A_SKV;
    float* sPT = sm + A_SPT;
    float* sRed = sm + A_SRED;
    float* sInv = sm + A_SINV;

    const int tid = threadIdx.x;
    const int h = blockIdx.x;
    const int bs = blockIdx.y;
    const float NEG_INF = -INFINITY;

    {
        const int lr = tid >> 4;
        const int lc = (tid & 15) << 2;
#pragma unroll
        for (int it = 0; it < 4; ++it) {
            const int qi = lr + (it << 4);
            float4 v = *(const float4*)(Q + ((size_t)bs * NQ + qi) * EMBED_DIM + h * HEAD_DIM + lc);
            float* dst = &sQ[qi * AQ_STRIDE + lc];
            dst[0] = v.x * 0.125f;
            dst[1] = v.y * 0.125f;
            dst[2] = v.z * 0.125f;
            dst[3] = v.w * 0.125f;
        }
    }

    auto load_chunk = [&](const float* base) {
#pragma unroll
        for (int it = 0; it < 4; ++it) {
            const int idx = tid + (it << 8);
            const int e = idx >> 4;
            const int c = idx & 15;
            float4 v = *(const float4*)(base + (size_t)e * (2 * EMBED_DIM) + (c << 2));
            *(float4*)&sKV[(e << 6) + (((c + e) & 15) << 2)] = v;
        }
    };

    const int qg = tid >> 4;
    const int kt = tid & 15;

    for (int c4 = 0; c4 < 4; ++c4) {
        __syncthreads();
        load_chunk(KV + ((size_t)bs * NE + (c4 << 6)) * (2 * EMBED_DIM) + h * HEAD_DIM);
        __syncthreads();

        float acc[4][4];
#pragma unroll
        for (int i = 0; i < 4; ++i)
#pragma unroll
            for (int j = 0; j < 4; ++j) acc[i][j] = 0.f;

#pragma unroll
        for (int d4 = 0; d4 < 16; ++d4) {
            float4 q4[4];
#pragma unroll
            for (int i = 0; i < 4; ++i)
                q4[i] = *(const float4*)&sQ[((qg << 2) + i) * AQ_STRIDE + (d4 << 2)];
#pragma unroll
            for (int j = 0; j < 4; ++j) {
                const int e = kt + (j << 4);
                float4 k4 = *(const float4*)&sKV[(e << 6) + (((d4 + e) & 15) << 2)];
#pragma unroll
                for (int i = 0; i < 4; ++i) {
                    acc[i][j] = fmaf(q4[i].x, k4.x, acc[i][j]);
                    acc[i][j] = fmaf(q4[i].y, k4.y, acc[i][j]);
                    acc[i][j] = fmaf(q4[i].z, k4.z, acc[i][j]);
                    acc[i][j] = fmaf(q4[i].w, k4.w, acc[i][j]);
                }
            }
        }
#pragma unroll
        for (int j = 0; j < 4; ++j) {
            const int kglob = (c4 << 6) + kt + (j << 4);
            float4 v;
            v.x = acc[0][j]; v.y = acc[1][j]; v.z = acc[2][j]; v.w = acc[3][j];
            *(float4*)&sPT[kglob * APT_STRIDE + (qg << 2)] = v;
        }
    }
    __syncthreads();

    {
        const int row = tid >> 2;
        const int part = tid & 3;
        const int kbeg = part << 6;

        const int4* mrow = (const int4*)(pre_mask + ((size_t)bs * NQ + row) * NE + kbeg);
        uint64_t bits = 0;
#pragma unroll
        for (int g = 0; g < 16; ++g) {
            int4 m = mrow[g];
            uint64_t b = (uint64_t)(m.x != 0) | ((uint64_t)(m.y != 0) << 1) |
                         ((uint64_t)(m.z != 0) << 2) | ((uint64_t)(m.w != 0) << 3);
            bits |= b << (g << 2);
        }

        float mx = NEG_INF;
#pragma unroll 8
        for (int k = 0; k < 64; ++k) {
            if (!((bits >> k) & 1ull))
                mx = fmaxf(mx, sPT[(kbeg + k) * APT_STRIDE + row]);
        }
        sRed[(row << 2) + part] = mx;
        __syncthreads();
        const float rm = fmaxf(fmaxf(sRed[row << 2], sRed[(row << 2) + 1]),
                               fmaxf(sRed[(row << 2) + 2], sRed[(row << 2) + 3]));
        __syncthreads();

        const bool live = (rm != NEG_INF);
        float ssum = 0.f;
#pragma unroll 8
        for (int k = 0; k < 64; ++k) {
            float* p = &sPT[(kbeg + k) * APT_STRIDE + row];
            float e = 0.f;
            if (live && !((bits >> k) & 1ull)) e = __expf(*p - rm);
            *p = e;
            ssum += e;
        }
        sRed[(row << 2) + part] = ssum;
        __syncthreads();
        if (tid < 64) {
            const float t = sRed[tid << 2] + sRed[(tid << 2) + 1] +
                            sRed[(tid << 2) + 2] + sRed[(tid << 2) + 3];
            sInv[tid] = (t > 0.f) ? (1.f / t) : 0.f;
        }
    }

    const int qg2 = tid & 15;
    const int dg = tid >> 4;

    float acc2[4][4];
#pragma unroll
    for (int i = 0; i < 4; ++i)
#pragma unroll
        for (int l = 0; l < 4; ++l) acc2[i][l] = 0.f;

    for (int c4 = 0; c4 < 4; ++c4) {
        __syncthreads();
        load_chunk(KV + ((size_t)bs * NE + (c4 << 6)) * (2 * EMBED_DIM) + EMBED_DIM + h * HEAD_DIM);
        __syncthreads();

#pragma unroll 4
        for (int e = 0; e < 64; ++e) {
            const int kglob = (c4 << 6) + e;
            float4 w4 = *(const float4*)&sPT[kglob * APT_STRIDE + (qg2 << 2)];
            float4 v4 = *(const float4*)&sKV[(e << 6) + ((((dg) + e) & 15) << 2)];
            acc2[0][0] = fmaf(w4.x, v4.x, acc2[0][0]);
            acc2[0][1] = fmaf(w4.x, v4.y, acc2[0][1]);
            acc2[0][2] = fmaf(w4.x, v4.z, acc2[0][2]);
            acc2[0][3] = fmaf(w4.x, v4.w, acc2[0][3]);
            acc2[1][0] = fmaf(w4.y, v4.x, acc2[1][0]);
            acc2[1][1] = fmaf(w4.y, v4.y, acc2[1][1]);
            acc2[1][2] = fmaf(w4.y, v4.z, acc2[1][2]);
            acc2[1][3] = fmaf(w4.y, v4.w, acc2[1][3]);
            acc2[2][0] = fmaf(w4.z, v4.x, acc2[2][0]);
            acc2[2][1] = fmaf(w4.z, v4.y, acc2[2][1]);
            acc2[2][2] = fmaf(w4.z, v4.z, acc2[2][2]);
            acc2[2][3] = fmaf(w4.z, v4.w, acc2[2][3]);
            acc2[3][0] = fmaf(w4.w, v4.x, acc2[3][0]);
            acc2[3][1] = fmaf(w4.w, v4.y, acc2[3][1]);
            acc2[3][2] = fmaf(w4.w, v4.z, acc2[3][2]);
            acc2[3][3] = fmaf(w4.w, v4.w, acc2[3][3]);
        }
    }

#pragma unroll
    for (int i = 0; i < 4; ++i) {
        const int qi = (qg2 << 2) + i;
        const float inv = sInv[qi];
        float4 v;
        v.x = acc2[i][0] * inv;
        v.y = acc2[i][1] * inv;
        v.z = acc2[i][2] * inv;
        v.w = acc2[i][3] * inv;
        *(float4*)(ATTN + ((size_t)bs * NQ + qi) * EMBED_DIM + h * HEAD_DIM + (dg << 2)) = v;
    }
}

// ---------------------------------------------------------------------------
// kernel_launch
// ---------------------------------------------------------------------------
extern "C" void kernel_launch(void* const* d_in, const int* in_sizes, int n_in,
                              void* d_out, int out_size)
{
    const float* entities  = (const float*)d_in[0];
    const int*   pre_mask  = (const int*)d_in[1];
    const int*   post_mask = (const int*)d_in[2];
    const float* W_in      = (const float*)d_in[3];
    const float* W_out     = (const float*)d_in[4];
    const float* b_out     = (const float*)d_in[5];
    float* out = (float*)d_out;

    float *Qs, *KVs, *ATs;
    __nv_bfloat16 *eh, *el, *qh, *ql, *ah, *al, *wih, *wil, *woh, *wol;
    cudaGetSymbolAddress((void**)&Qs, g_Q);
    cudaGetSymbolAddress((void**)&KVs, g_KV);
    cudaGetSymbolAddress((void**)&ATs, g_ATTN);
    cudaGetSymbolAddress((void**)&eh, g_ent_hi);
    cudaGetSymbolAddress((void**)&el, g_ent_lo);
    cudaGetSymbolAddress((void**)&qh, g_q_hi);
    cudaGetSymbolAddress((void**)&ql, g_q_lo);
    cudaGetSymbolAddress((void**)&ah, g_attn_hi);
    cudaGetSymbolAddress((void**)&al, g_attn_lo);
    cudaGetSymbolAddress((void**)&wih, g_WinT_hi);
    cudaGetSymbolAddress((void**)&wil, g_WinT_lo);
    cudaGetSymbolAddress((void**)&woh, g_WoutT_hi);
    cudaGetSymbolAddress((void**)&wol, g_WoutT_lo);

    cudaFuncSetAttribute(gemm_bf16x3<false>,
                         cudaFuncAttributeMaxDynamicSharedMemorySize, GEMM_DYN_SMEM);
    cudaFuncSetAttribute(gemm_bf16x3<true>,
                         cudaFuncAttributeMaxDynamicSharedMemorySize, GEMM_DYN_SMEM);
    cudaFuncSetAttribute(attn_kernel,
                         cudaFuncAttributeMaxDynamicSharedMemorySize, ATTN_SMEM_BYTES);

    // 1) split entities -> tiled bf16 hi/lo (+ compact Q rows)
    {
        int units = (BS * NE) << 6;   // 8.4M
        split_tiledA<<<(units + 255) / 256, 256>>>(entities, eh, el, qh, ql, BS * NE, 1);
    }
    // 2) split+transpose weights -> tiled
    {
        int u1 = QKV_DIM << 6;
        splitT_tiled<<<(u1 + 255) / 256, 256>>>(W_in, wih, wil, QKV_DIM);
        int u2 = OUT_DIM << 6;
        splitT_tiled<<<(u2 + 255) / 256, 256>>>(W_out, woh, wol, OUT_DIM);
    }
    // 3) Q = q_ent @ W_in[:, 0:512]   (compact A)  M=32768, N=512
    gemm_bf16x3<false><<<dim3(EMBED_DIM / 128, (BS * NQ) / 128), 256, GEMM_DYN_SMEM>>>(
        qh, ql, wih, wil, Qs, EMBED_DIM, nullptr, nullptr);

    // 4) KV = entities @ W_in[:, 512:1536]  (B = panels 4..11: offset 4*8*8192 elems)
    gemm_bf16x3<false><<<dim3((2 * EMBED_DIM) / 128, (BS * NE) / 128), 256, GEMM_DYN_SMEM>>>(
        eh, el, wih + 262144, wil + 262144, KVs, 2 * EMBED_DIM, nullptr, nullptr);

    // 5) attention
    attn_kernel<<<dim3(N_HEADS, BS), 256, ATTN_SMEM_BYTES>>>(Qs, KVs, pre_mask, ATs);

    // 6) split ATTN -> tiled bf16 hi/lo
    {
        int units = (BS * NQ) << 6;
        split_tiledA<<<(units + 255) / 256, 256>>>(ATs, ah, al, nullptr, nullptr, BS * NQ, 0);
    }
    // 7) out = ATTN @ W_out + b_out, post-masked
    gemm_bf16x3<true><<<dim3(OUT_DIM / 128, (BS * NQ) / 128), 256, GEMM_DYN_SMEM>>>(
        ah, al, woh, wol, out, OUT_DIM, b_out, post_mask);
}